// round 1
// baseline (speedup 1.0000x reference)
#include <cuda_runtime.h>
#include <math.h>

// ---------------------------------------------------------------------------
// Problem constants (fixed by setup_inputs)
// ---------------------------------------------------------------------------
#define BSZ     4
#define LSEQ    4096
#define DM      1048          // d_model
#define PD      1048          // state dim
#define NLAYERS 3
#define MROWS   (BSZ*LSEQ)    // 16384
#define MD      ((size_t)MROWS * DM)   // 17,170,432

// Scratch: 12 activation planes of [M, D] (H2 uses 2) + pooled
//   0:H 1:FX 2:GRE 3:GIM 4:XRE 5:XIM 6:Y 7:FY 8:T 9:Z 10..11:H2  + POOL
__device__ float g_scratch[12ULL * 17170432ULL + 8192ULL];

__device__ __forceinline__ float gelu_exact(float x) {
    return 0.5f * x * (1.0f + erff(x * 0.70710678118654752f));
}

// ---------------------------------------------------------------------------
// SGEMM: C[M,N] = alpha * A[M,K] @ W[N,K]^T + beta * C
// Both A and W are K-contiguous (row-major [rows, K]).
// 128x128 block tile, BK=8, 8x8 thread tile, 256 threads.
// Requires: M % 128 == 0, K % 8 == 0, K % 4 == 0 (float4 loads). N arbitrary.
// ---------------------------------------------------------------------------
__global__ __launch_bounds__(256) void sgemm_tn(
    const float* __restrict__ A, const float* __restrict__ W,
    float* __restrict__ C, int M, int N, int K, float alpha, float beta)
{
    constexpr int BM = 128, BN = 128, BK = 8, TM = 8, TN = 8;
    __shared__ __align__(16) float As[BK][BM];
    __shared__ __align__(16) float Ws[BK][BN];

    const int tid  = threadIdx.x;
    const int trow = tid >> 4;   // 0..15
    const int tcol = tid & 15;   // 0..15

    const int loadRow = tid >> 1;        // 0..127
    const int loadCol = (tid & 1) * 4;   // 0 or 4

    const size_t aBase = (size_t)(blockIdx.y * BM + loadRow) * K + loadCol;
    const int    wN    = blockIdx.x * BN + loadRow;
    const size_t wBase = (size_t)wN * K + loadCol;
    const bool   wOk   = (wN < N);

    float acc[TM][TN] = {};

    for (int k0 = 0; k0 < K; k0 += BK) {
        float4 av = *reinterpret_cast<const float4*>(A + aBase + k0);
        float4 wv = wOk ? *reinterpret_cast<const float4*>(W + wBase + k0)
                        : make_float4(0.f, 0.f, 0.f, 0.f);
        As[loadCol + 0][loadRow] = av.x;
        As[loadCol + 1][loadRow] = av.y;
        As[loadCol + 2][loadRow] = av.z;
        As[loadCol + 3][loadRow] = av.w;
        Ws[loadCol + 0][loadRow] = wv.x;
        Ws[loadCol + 1][loadRow] = wv.y;
        Ws[loadCol + 2][loadRow] = wv.z;
        Ws[loadCol + 3][loadRow] = wv.w;
        __syncthreads();

        #pragma unroll
        for (int kk = 0; kk < BK; kk++) {
            float ra[TM], rb[TN];
            float4 a0 = *reinterpret_cast<const float4*>(&As[kk][trow * TM]);
            float4 a1 = *reinterpret_cast<const float4*>(&As[kk][trow * TM + 4]);
            float4 b0 = *reinterpret_cast<const float4*>(&Ws[kk][tcol * TN]);
            float4 b1 = *reinterpret_cast<const float4*>(&Ws[kk][tcol * TN + 4]);
            ra[0]=a0.x; ra[1]=a0.y; ra[2]=a0.z; ra[3]=a0.w;
            ra[4]=a1.x; ra[5]=a1.y; ra[6]=a1.z; ra[7]=a1.w;
            rb[0]=b0.x; rb[1]=b0.y; rb[2]=b0.z; rb[3]=b0.w;
            rb[4]=b1.x; rb[5]=b1.y; rb[6]=b1.z; rb[7]=b1.w;
            #pragma unroll
            for (int i = 0; i < TM; i++)
                #pragma unroll
                for (int j = 0; j < TN; j++)
                    acc[i][j] = fmaf(ra[i], rb[j], acc[i][j]);
        }
        __syncthreads();
    }

    const int mBase = blockIdx.y * BM + trow * TM;
    const int nBase = blockIdx.x * BN + tcol * TN;
    #pragma unroll
    for (int i = 0; i < TM; i++) {
        size_t rowOff = (size_t)(mBase + i) * N;
        #pragma unroll
        for (int j = 0; j < TN; j++) {
            int n = nBase + j;
            if (n < N) {
                float v = alpha * acc[i][j];
                if (beta != 0.f) v = fmaf(beta, C[rowOff + n], v);
                C[rowOff + n] = v;
            }
        }
    }
}

// ---------------------------------------------------------------------------
// Elementwise / row kernels
// ---------------------------------------------------------------------------
__global__ void enc_kernel(const float* __restrict__ x,
                           const float* __restrict__ ew,
                           const float* __restrict__ eb,
                           float* __restrict__ H)
{
    size_t i = (size_t)blockIdx.x * blockDim.x + threadIdx.x;
    if (i >= MD) return;
    int d = (int)(i % DM);
    int m = (int)(i / DM);
    H[i] = fmaf(x[m], ew[d], eb[d]);
}

// fx = LN( LN(h, w1, b1), w2, b2 )   one block per row
__global__ __launch_bounds__(256) void ln2_kernel(
    const float* __restrict__ X, float* __restrict__ O,
    const float* __restrict__ w1, const float* __restrict__ b1,
    const float* __restrict__ w2, const float* __restrict__ b2)
{
    const int row = blockIdx.x;
    const int tid = threadIdx.x;
    const float* x = X + (size_t)row * DM;
    float* o = O + (size_t)row * DM;
    __shared__ float sA[256], sB[256];

    float v[5];
    float s = 0.f, ss = 0.f;
    #pragma unroll
    for (int k = 0; k < 5; k++) {
        int d = tid + k * 256;
        float t = (d < DM) ? x[d] : 0.f;
        v[k] = t; s += t; ss += t * t;
    }
    sA[tid] = s; sB[tid] = ss; __syncthreads();
    for (int st = 128; st > 0; st >>= 1) {
        if (tid < st) { sA[tid] += sA[tid + st]; sB[tid] += sB[tid + st]; }
        __syncthreads();
    }
    float mu  = sA[0] * (1.0f / DM);
    float var = sB[0] * (1.0f / DM) - mu * mu;
    float rs  = rsqrtf(var + 1e-5f);
    __syncthreads();

    s = 0.f; ss = 0.f;
    #pragma unroll
    for (int k = 0; k < 5; k++) {
        int d = tid + k * 256;
        float r = 0.f;
        if (d < DM) r = fmaf((v[k] - mu) * rs, w1[d], b1[d]);
        v[k] = r; s += r; ss += r * r;
    }
    sA[tid] = s; sB[tid] = ss; __syncthreads();
    for (int st = 128; st > 0; st >>= 1) {
        if (tid < st) { sA[tid] += sA[tid + st]; sB[tid] += sB[tid + st]; }
        __syncthreads();
    }
    float mu2  = sA[0] * (1.0f / DM);
    float var2 = sB[0] * (1.0f / DM) - mu2 * mu2;
    float rs2  = rsqrtf(var2 + 1e-5f);
    #pragma unroll
    for (int k = 0; k < 5; k++) {
        int d = tid + k * 256;
        if (d < DM) o[d] = fmaf((v[k] - mu2) * rs2, w2[d], b2[d]);
    }
}

// fy = LN( gelu(Y + Dvec*fx) + fx , w, b )   one block per row
__global__ __launch_bounds__(256) void postln_kernel(
    const float* __restrict__ Y, const float* __restrict__ FX,
    const float* __restrict__ dv,
    const float* __restrict__ w, const float* __restrict__ b,
    float* __restrict__ O)
{
    const int row = blockIdx.x;
    const int tid = threadIdx.x;
    const float* y  = Y  + (size_t)row * DM;
    const float* fx = FX + (size_t)row * DM;
    float* o = O + (size_t)row * DM;
    __shared__ float sA[256], sB[256];

    float v[5];
    float s = 0.f, ss = 0.f;
    #pragma unroll
    for (int k = 0; k < 5; k++) {
        int d = tid + k * 256;
        float z = 0.f;
        if (d < DM) {
            float f = fx[d];
            float e = fmaf(dv[d], f, y[d]);
            z = gelu_exact(e) + f;
        }
        v[k] = z; s += z; ss += z * z;
    }
    sA[tid] = s; sB[tid] = ss; __syncthreads();
    for (int st = 128; st > 0; st >>= 1) {
        if (tid < st) { sA[tid] += sA[tid + st]; sB[tid] += sB[tid + st]; }
        __syncthreads();
    }
    float mu  = sA[0] * (1.0f / DM);
    float var = sB[0] * (1.0f / DM) - mu * mu;
    float rs  = rsqrtf(var + 1e-5f);
    #pragma unroll
    for (int k = 0; k < 5; k++) {
        int d = tid + k * 256;
        if (d < DM) o[d] = fmaf((v[k] - mu) * rs, w[d], b[d]);
    }
}

// Sequential ZOH scan per (b, p). coef = (Abar-1)/Lambda is folded in here.
__global__ void scan_kernel(
    const float* __restrict__ GRE, const float* __restrict__ GIM,
    float* __restrict__ XRE, float* __restrict__ XIM,
    const float* __restrict__ lr_, const float* __restrict__ li_,
    const float* __restrict__ ls_)
{
    int t = blockIdx.x * blockDim.x + threadIdx.x;
    if (t >= BSZ * PD) return;
    int b = t / PD, p = t % PD;

    float lr = lr_[p], li = li_[p];
    float st = expf(ls_[p]);
    float er = expf(lr * st);
    float sn, cs; sincosf(li * st, &sn, &cs);
    float ar = er * cs, ai = er * sn;          // Abar
    float inv = 1.0f / (lr * lr + li * li);
    float nr = ar - 1.0f;
    float cr = (nr * lr + ai * li) * inv;      // (Abar-1)/Lambda
    float ci = (ai * lr - nr * li) * inv;

    size_t off = (size_t)b * LSEQ * PD + p;
    const float* gr = GRE + off;
    const float* gi = GIM + off;
    float* xro = XRE + off;
    float* xio = XIM + off;

    float xr = 0.f, xi = 0.f;
    #pragma unroll 4
    for (int l = 0; l < LSEQ; l++) {
        float ur = gr[(size_t)l * PD];
        float ui = gi[(size_t)l * PD];
        float br = fmaf(cr, ur, -ci * ui);
        float bi = fmaf(cr, ui,  ci * ur);
        float nxr = fmaf(ar, xr, fmaf(-ai, xi, br));
        float nxi = fmaf(ar, xi, fmaf( ai, xr, bi));
        xr = nxr; xi = nxi;
        xro[(size_t)l * PD] = xr;
        xio[(size_t)l * PD] = xi;
    }
}

// GEGLU: T[m,d] = H2[m,d] * gelu(H2[m, DM+d]),  H2 row stride = 2*DM
__global__ void geglu_kernel(const float* __restrict__ H2, float* __restrict__ T)
{
    size_t i = (size_t)blockIdx.x * blockDim.x + threadIdx.x;
    if (i >= MD) return;
    int d = (int)(i % DM);
    size_t m = i / DM;
    const float* r = H2 + m * (size_t)(2 * DM);
    T[i] = r[d] * gelu_exact(r[DM + d]);
}

// h += Z + fy
__global__ void addres_kernel(float* __restrict__ H,
                              const float* __restrict__ Z,
                              const float* __restrict__ FY)
{
    size_t i = (size_t)blockIdx.x * blockDim.x + threadIdx.x;
    if (i >= MD) return;
    H[i] += Z[i] + FY[i];
}

__global__ void zero_kernel(float* __restrict__ P, int n)
{
    int i = blockIdx.x * blockDim.x + threadIdx.x;
    if (i < n) P[i] = 0.f;
}

// partial sums over L chunks into POOL via atomics; blockIdx.y = chunk
#define POOL_CHUNKS 32
__global__ void pool_kernel(const float* __restrict__ H, float* __restrict__ POOL)
{
    int t = blockIdx.x * blockDim.x + threadIdx.x;
    if (t >= BSZ * DM) return;
    int b = t / DM, d = t % DM;
    const int CL = LSEQ / POOL_CHUNKS;   // 128
    int l0 = blockIdx.y * CL;
    const float* h = H + (size_t)b * LSEQ * DM + (size_t)l0 * DM + d;
    float s = 0.f;
    #pragma unroll 8
    for (int l = 0; l < CL; l++) s += h[(size_t)l * DM];
    atomicAdd(&POOL[t], s);
}

__global__ void head_kernel(const float* __restrict__ POOL,
                            const float* __restrict__ hw,
                            const float* __restrict__ hb,
                            float* __restrict__ out)
{
    int b = blockIdx.x;
    int tid = threadIdx.x;
    __shared__ float sA[256];
    float s = 0.f;
    for (int d = tid; d < DM; d += 256) s = fmaf(POOL[b * DM + d], hw[d], s);
    sA[tid] = s; __syncthreads();
    for (int st = 128; st > 0; st >>= 1) {
        if (tid < st) sA[tid] += sA[tid + st];
        __syncthreads();
    }
    if (tid == 0) out[b] = sA[0] * (1.0f / LSEQ) + hb[0];
}

// ---------------------------------------------------------------------------
// kernel_launch
// ---------------------------------------------------------------------------
extern "C" void kernel_launch(void* const* d_in, const int* in_sizes, int n_in,
                              void* d_out, int out_size)
{
    const float* x           = (const float*)d_in[0];
    const float* enc_w       = (const float*)d_in[1];
    const float* enc_b       = (const float*)d_in[2];
    const float* norm_w      = (const float*)d_in[3];
    const float* norm_b      = (const float*)d_in[4];
    const float* attn_norm_w = (const float*)d_in[5];
    const float* attn_norm_b = (const float*)d_in[6];
    const float* ff_norm_w   = (const float*)d_in[7];
    const float* ff_norm_b   = (const float*)d_in[8];
    const float* lam_re      = (const float*)d_in[9];
    const float* lam_im      = (const float*)d_in[10];
    const float* log_step    = (const float*)d_in[11];
    const float* B_re        = (const float*)d_in[12];
    const float* B_im        = (const float*)d_in[13];
    const float* C_re        = (const float*)d_in[14];
    const float* C_im        = (const float*)d_in[15];
    const float* Dvec        = (const float*)d_in[16];
    const float* Wenc        = (const float*)d_in[17];
    const float* Wdec        = (const float*)d_in[18];
    const float* head_w      = (const float*)d_in[19];
    const float* head_b      = (const float*)d_in[20];
    float* out = (float*)d_out;

    float* base = nullptr;
    cudaGetSymbolAddress((void**)&base, g_scratch);
    float* H    = base + 0 * MD;
    float* FX   = base + 1 * MD;
    float* GRE  = base + 2 * MD;
    float* GIM  = base + 3 * MD;
    float* XRE  = base + 4 * MD;
    float* XIM  = base + 5 * MD;
    float* Y    = base + 6 * MD;
    float* FY   = base + 7 * MD;
    float* T    = base + 8 * MD;
    float* Z    = base + 9 * MD;
    float* H2   = base + 10 * MD;
    float* POOL = base + 12 * MD;

    const int EW_BLOCKS = (int)((MD + 255) / 256);

    // Encoder: h = x @ enc_w.T + enc_b
    enc_kernel<<<EW_BLOCKS, 256>>>(x, enc_w, enc_b, H);

    dim3 gN((PD + 127) / 128, MROWS / 128);          // N = 1048
    dim3 gN2((2 * DM + 127) / 128, MROWS / 128);     // N = 2096

    for (int i = 0; i < NLAYERS; i++) {
        const float* nw  = norm_w      + (size_t)i * DM;
        const float* nb  = norm_b      + (size_t)i * DM;
        const float* aw  = attn_norm_w + (size_t)i * DM;
        const float* ab  = attn_norm_b + (size_t)i * DM;
        const float* fw  = ff_norm_w   + (size_t)i * DM;
        const float* fb  = ff_norm_b   + (size_t)i * DM;
        const float* lre = lam_re      + (size_t)i * PD;
        const float* lim = lam_im      + (size_t)i * PD;
        const float* lst = log_step    + (size_t)i * PD;
        const float* bre = B_re + (size_t)i * PD * DM;
        const float* bim = B_im + (size_t)i * PD * DM;
        const float* cre = C_re + (size_t)i * DM * PD;
        const float* cim = C_im + (size_t)i * DM * PD;
        const float* dv  = Dvec + (size_t)i * DM;
        const float* we  = Wenc + (size_t)i * 2 * DM * DM;
        const float* wd  = Wdec + (size_t)i * DM * DM;

        // fx = LN(LN(h, norm), attn_norm)
        ln2_kernel<<<MROWS, 256>>>(H, FX, nw, nb, aw, ab);

        // G = fx @ B^T  (real and imag parts)
        sgemm_tn<<<gN, 256>>>(FX, bre, GRE, MROWS, PD, DM, 1.f, 0.f);
        sgemm_tn<<<gN, 256>>>(FX, bim, GIM, MROWS, PD, DM, 1.f, 0.f);

        // recurrent scan (applies ZOH coefficient)
        scan_kernel<<<(BSZ * PD + 127) / 128, 128>>>(GRE, GIM, XRE, XIM, lre, lim, lst);

        // Y = Re(xs @ C^T) = xs_re @ C_re^T - xs_im @ C_im^T
        sgemm_tn<<<gN, 256>>>(XRE, cre, Y, MROWS, DM, PD, 1.f, 0.f);
        sgemm_tn<<<gN, 256>>>(XIM, cim, Y, MROWS, DM, PD, -1.f, 1.f);

        // fy = LN(gelu(Y + Dvec*fx) + fx)
        postln_kernel<<<MROWS, 256>>>(Y, FX, dv, fw, fb, FY);

        // GEGLU MLP
        sgemm_tn<<<gN2, 256>>>(FY, we, H2, MROWS, 2 * DM, DM, 1.f, 0.f);
        geglu_kernel<<<EW_BLOCKS, 256>>>(H2, T);
        sgemm_tn<<<gN, 256>>>(T, wd, Z, MROWS, DM, DM, 1.f, 0.f);

        // h += Z + fy
        addres_kernel<<<EW_BLOCKS, 256>>>(H, Z, FY);
    }

    // mean over L, then head projection
    zero_kernel<<<(BSZ * DM + 255) / 256, 256>>>(POOL, BSZ * DM);
    dim3 gp((BSZ * DM + 127) / 128, POOL_CHUNKS);
    pool_kernel<<<gp, 128>>>(H, POOL);
    head_kernel<<<BSZ, 256>>>(POOL, head_w, head_b, out);
}

// round 3
// speedup vs baseline: 1.0395x; 1.0395x over previous
#include <cuda_runtime.h>
#include <cuda_bf16.h>
#include <math.h>
#include <cstdint>

// ---------------------------------------------------------------------------
// Problem constants
// ---------------------------------------------------------------------------
#define BSZ     4
#define LSEQ    4096
#define DM      1048
#define PD      1048
#define NLAYERS 3
#define MROWS   (BSZ*LSEQ)              // 16384
#define MD      ((size_t)MROWS * DM)    // 17,170,432
#define KP      1088                    // K padded to multiple of 64
#define NCHUNK  (KP/64)                 // 17
#define NP1     1152                    // 1048 padded to 128 (9 tiles)
#define NP2     2176                    // 2096 padded to 128 (17 tiles)

// sizes in floats
#define MD_F   17170432ULL
#define ACT_F  8912896ULL               // (16384*1088 bf16)/2
#define W1_F   626688ULL                // (1152*1088 bf16)/2
#define W2_F   1183744ULL               // (2176*1088 bf16)/2
#define WL_F   (10ULL*W1_F + 2ULL*W2_F) // per-layer weights

#define OFF_H    0ULL
#define OFF_GRE  (1ULL*MD_F)
#define OFF_GIM  (2ULL*MD_F)
#define OFF_Y    (3ULL*MD_F)
#define OFF_Z    (4ULL*MD_F)
#define OFF_H2   (5ULL*MD_F)
#define OFF_ACT  (7ULL*MD_F)
#define OFF_WB   (OFF_ACT + 10ULL*ACT_F)
#define OFF_POOL (OFF_WB + 3ULL*WL_F)
#define TOT_F    (OFF_POOL + 8192ULL)

__device__ __align__(1024) float g_scratch[TOT_F];

__device__ __forceinline__ float gelu_exact(float x) {
    return 0.5f * x * (1.0f + erff(x * 0.70710678118654752f));
}

// Arch guard: tcgen05 only exists in the sm_103a-specific compile pass.
// The compute_103 (non-'a') PTX pass compiles the slow fallback, which never
// runs as long as the fatbin carries sm_103a SASS (it does).
#if defined(__CUDA_ARCH_FEAT_SM103_ALL) || defined(__CUDA_ARCH_SPECIFIC__) || defined(__CUDA_ARCH_FEAT_SM100_ALL)
#define HAS_TCGEN05 1
#else
#define HAS_TCGEN05 0
#endif

// ---------------------------------------------------------------------------
// PTX helpers (tcgen05 / mbarrier)
// ---------------------------------------------------------------------------
__device__ __forceinline__ uint32_t elect_one_pred() {
    uint32_t pred;
    asm volatile(
        "{\n\t.reg .pred p;\n\telect.sync _|p, 0xFFFFFFFF;\n\t"
        "selp.b32 %0, 1, 0, p;\n\t}" : "=r"(pred));
    return pred;
}
__device__ __forceinline__ uint32_t smem_u32_of(const void* p) {
    uint32_t a;
    asm("{ .reg .u64 t; cvta.to.shared.u64 t, %1; cvt.u32.u64 %0, t; }"
        : "=r"(a) : "l"(p));
    return a;
}

#define TCGEN05_ALLOC(smem_result_addr, nCols) \
    asm volatile("tcgen05.alloc.cta_group::1.sync.aligned.shared::cta.b32 [%0], %1;" \
        :: "r"((uint32_t)(smem_result_addr)), "r"((uint32_t)(nCols)) : "memory")
#define TCGEN05_DEALLOC(tmem_addr, nCols) \
    asm volatile("tcgen05.dealloc.cta_group::1.sync.aligned.b32 %0, %1;" \
        :: "r"(tmem_addr), "r"((uint32_t)(nCols)))
#define TCGEN05_RELINQUISH() \
    asm volatile("tcgen05.relinquish_alloc_permit.cta_group::1.sync.aligned;")
#define TCGEN05_COMMIT(mbar_smem_addr) \
    asm volatile("tcgen05.commit.cta_group::1.mbarrier::arrive::one.shared::cluster.b64 [%0];" \
        :: "r"((uint32_t)(mbar_smem_addr)) : "memory")
#define TCGEN05_FENCE_AFTER() \
    asm volatile("tcgen05.fence::after_thread_sync;" ::: "memory")
#define TCGEN05_WAIT_LD() \
    asm volatile("tcgen05.wait::ld.sync.aligned;" ::: "memory")
#define FENCE_PROXY_ASYNC_SHARED_CTA() \
    asm volatile("fence.proxy.async.shared::cta;" ::: "memory")
#define MBARRIER_INIT(mbar_smem_addr, count) \
    asm volatile("mbarrier.init.shared.b64 [%0], %1;" \
        :: "r"((uint32_t)(mbar_smem_addr)), "r"((uint32_t)(count)) : "memory")
#define MBARRIER_WAIT_PARITY(mbar_smem_addr, phase_parity) do { \
    uint32_t _mbar = (uint32_t)(mbar_smem_addr); \
    uint32_t _parity = (uint32_t)(phase_parity); \
    uint32_t _done; \
    asm volatile( \
        "{\n\t.reg .pred p;\n\t" \
        "mbarrier.try_wait.parity.acquire.cta.shared::cta.b64 p, [%1], %2;\n\t" \
        "selp.b32 %0, 1, 0, p;\n\t}" \
        : "=r"(_done) : "r"(_mbar), "r"(_parity) : "memory"); \
    if (!_done) { \
        asm volatile( \
            "{\n\t.reg .pred P1;\n\t" \
            "WAIT_LOOP_%=:\n\t" \
            "mbarrier.try_wait.parity.acquire.cta.shared::cta.b64 P1, [%0], %1, 0x989680;\n\t" \
            "@P1 bra.uni WAIT_DONE_%=;\n\t" \
            "bra.uni WAIT_LOOP_%=;\n\t" \
            "WAIT_DONE_%=:\n\t}" \
            :: "r"(_mbar), "r"(_parity) : "memory"); \
    } \
} while(0)
#define STS128(r0, r1, r2, r3, smem_addr) \
    asm volatile("st.shared.v4.b32 [%0], {%1, %2, %3, %4};" \
        :: "r"(smem_addr), "r"(r0), "r"(r1), "r"(r2), "r"(r3) : "memory")
#define TCGEN05_LD_32X32B_X32(r, tmem_addr) \
    asm volatile( \
        "tcgen05.ld.sync.aligned.32x32b.x32.b32 " \
        "{%0, %1, %2, %3, %4, %5, %6, %7, " \
        " %8, %9, %10, %11, %12, %13, %14, %15, " \
        " %16, %17, %18, %19, %20, %21, %22, %23, " \
        " %24, %25, %26, %27, %28, %29, %30, %31}, [%32];" \
        : "=r"((r)[0]),  "=r"((r)[1]),  "=r"((r)[2]),  "=r"((r)[3]), \
          "=r"((r)[4]),  "=r"((r)[5]),  "=r"((r)[6]),  "=r"((r)[7]), \
          "=r"((r)[8]),  "=r"((r)[9]),  "=r"((r)[10]), "=r"((r)[11]), \
          "=r"((r)[12]), "=r"((r)[13]), "=r"((r)[14]), "=r"((r)[15]), \
          "=r"((r)[16]), "=r"((r)[17]), "=r"((r)[18]), "=r"((r)[19]), \
          "=r"((r)[20]), "=r"((r)[21]), "=r"((r)[22]), "=r"((r)[23]), \
          "=r"((r)[24]), "=r"((r)[25]), "=r"((r)[26]), "=r"((r)[27]), \
          "=r"((r)[28]), "=r"((r)[29]), "=r"((r)[30]), "=r"((r)[31]) \
        : "r"(tmem_addr))

// SW128, Blackwell, LBO=1, SBO=64 (K-major)
static constexpr uint64_t SMEM_DESC_BASE_SW128 =
    (uint64_t(2) << 61) | (uint64_t(1) << 46) | (uint64_t(64) << 32) | (uint64_t(1) << 16);
#define MAKE_SMEM_DESC(base_addr) \
    (SMEM_DESC_BASE_SW128 | ((uint64_t)((base_addr) >> 4) & 0x3FFF))

// idesc: kind::f16, dtype=F32, atype=btype=BF16, M=128, N=128
static constexpr uint32_t GIDESC =
    (1u<<4) | (1u<<7) | (1u<<10) | ((128u/8u)<<17) | ((128u/16u)<<24);

#if HAS_TCGEN05
__device__ __forceinline__ void mma_f16_ss(uint32_t d_tmem, uint64_t a_desc,
                                           uint64_t b_desc, uint32_t en) {
    asm volatile(
        "{\n\t.reg .pred p;\n\tsetp.ne.u32 p, %4, 0;\n\t"
        "tcgen05.mma.cta_group::1.kind::f16 [%0], %1, %2, %3, {%5, %5, %5, %5}, p;\n\t}"
        :: "r"(d_tmem), "l"(a_desc), "l"(b_desc), "r"(GIDESC), "r"(en), "r"(0u)
        : "memory");
}
#endif

__device__ __forceinline__ void split_bf16(float v, __nv_bfloat16& h, __nv_bfloat16& l) {
    h = __float2bfloat16(v);
    l = __float2bfloat16(v - __bfloat162float(h));
}

// ---------------------------------------------------------------------------
// tcgen05 bf16x3 GEMM: C[M,N] = alpha * (Ah+Al)[M,KP] @ (Bh+Bl)[N,KP]^T + beta*C
// Tiles 128x128x64, 2-stage smem pipeline, TMEM accumulator.
// Grid: (Npad/128, M/128), 128 threads.
// ---------------------------------------------------------------------------
#define GEMM_SMEM_BYTES (1024 + 2*65536)

__global__ __launch_bounds__(128) void gemm_bf16x3(
    const __nv_bfloat16* __restrict__ Ah, const __nv_bfloat16* __restrict__ Al,
    const __nv_bfloat16* __restrict__ Bh, const __nv_bfloat16* __restrict__ Bl,
    float* __restrict__ C, int N, float alpha, float beta)
{
#if HAS_TCGEN05
    extern __shared__ __align__(1024) char smem[];
    const uint32_t sbase = smem_u32_of(smem);
    const int tid = threadIdx.x;
    const int wid = tid >> 5;
    const int lid = tid & 31;

    if (wid == 0) {
        TCGEN05_ALLOC(sbase + 0, 128);
        TCGEN05_RELINQUISH();
    }
    if (tid == 0) { MBARRIER_INIT(sbase + 16, 1); MBARRIER_INIT(sbase + 24, 1); }
    __syncthreads();
    uint32_t tmem;
    asm volatile("ld.shared.b32 %0, [%1];" : "=r"(tmem) : "r"(sbase));

    const __nv_bfloat16* srcs[4];
    srcs[0] = Ah + (size_t)blockIdx.y * 128 * KP;
    srcs[1] = Al + (size_t)blockIdx.y * 128 * KP;
    srcs[2] = Bh + (size_t)blockIdx.x * 128 * KP;
    srcs[3] = Bl + (size_t)blockIdx.x * 128 * KP;

    int ph0 = 0, ph1 = 0;
    for (int kc = 0; kc < NCHUNK; kc++) {
        const int s = kc & 1;
        if (kc >= 2) {
            if (s == 0) { MBARRIER_WAIT_PARITY(sbase + 16, ph0); ph0 ^= 1; }
            else        { MBARRIER_WAIT_PARITY(sbase + 24, ph1); ph1 ^= 1; }
        }
        const int k0 = kc * 64;
        const uint32_t stBase = sbase + 1024 + s * 65536;
        #pragma unroll
        for (int t = 0; t < 4; t++) {
            const __nv_bfloat16* src = srcs[t];
            const uint32_t tb = stBase + t * 16384;
            #pragma unroll
            for (int i = 0; i < 8; i++) {
                int lin = i * 128 + tid;
                int row = lin >> 3;
                int j   = lin & 7;
                uint4 v = *reinterpret_cast<const uint4*>(src + (size_t)row * KP + k0 + j * 8);
                uint32_t off = (uint32_t)(row * 128 + j * 16);
                uint32_t sw  = off ^ ((off >> 3) & 0x70);
                STS128(v.x, v.y, v.z, v.w, tb + sw);
            }
        }
        __syncthreads();
        FENCE_PROXY_ASYNC_SHARED_CTA();
        if (wid == 0 && elect_one_pred()) {
            uint64_t dAh = MAKE_SMEM_DESC(stBase + 0);
            uint64_t dAl = MAKE_SMEM_DESC(stBase + 16384);
            uint64_t dBh = MAKE_SMEM_DESC(stBase + 32768);
            uint64_t dBl = MAKE_SMEM_DESC(stBase + 49152);
            #pragma unroll
            for (int ks = 0; ks < 4; ks++) {
                uint32_t en = (kc != 0) || (ks != 0);
                mma_f16_ss(tmem, dAh + ks * 2, dBh + ks * 2, en);
            }
            #pragma unroll
            for (int ks = 0; ks < 4; ks++) mma_f16_ss(tmem, dAh + ks * 2, dBl + ks * 2, 1u);
            #pragma unroll
            for (int ks = 0; ks < 4; ks++) mma_f16_ss(tmem, dAl + ks * 2, dBh + ks * 2, 1u);
            TCGEN05_COMMIT(s == 0 ? sbase + 16 : sbase + 24);
        }
    }
    // last chunk kc=16 -> stage 0
    MBARRIER_WAIT_PARITY(sbase + 16, ph0);
    TCGEN05_FENCE_AFTER();

    // epilogue: TMEM -> registers -> gmem
    float* sC = reinterpret_cast<float*>(smem + 1024);
    const int nbase = blockIdx.x * 128;
    const size_t mrow0 = (size_t)blockIdx.y * 128;
    for (int cb = 0; cb < 4; cb++) {
        uint32_t r[32];
        TCGEN05_LD_32X32B_X32(r, tmem + cb * 32);
        TCGEN05_WAIT_LD();
        #pragma unroll
        for (int c = 0; c < 32; c++) sC[(wid * 32 + lid) * 33 + c] = __uint_as_float(r[c]);
        __syncthreads();
        size_t rowOff = (mrow0 + tid) * (size_t)N;
        #pragma unroll
        for (int c = 0; c < 32; c++) {
            int n = nbase + cb * 32 + c;
            if (n < N) {
                float v = alpha * sC[tid * 33 + c];
                if (beta != 0.f) v = fmaf(beta, C[rowOff + n], v);
                C[rowOff + n] = v;
            }
        }
        __syncthreads();
    }
    if (wid == 0) TCGEN05_DEALLOC(tmem, 128);
#else
    // Fallback for the non-'a' PTX compile pass. Correct but slow; never runs
    // on hardware because the fatbin carries sm_103a SASS.
    const int tid = threadIdx.x;
    const size_t m = (size_t)blockIdx.y * 128 + tid;
    const int n0 = blockIdx.x * 128;
    const __nv_bfloat16* arh = Ah + m * KP;
    const __nv_bfloat16* arl = Al + m * KP;
    for (int j = 0; j < 128; j++) {
        int n = n0 + j;
        if (n >= N) break;
        const __nv_bfloat16* brh = Bh + (size_t)n * KP;
        const __nv_bfloat16* brl = Bl + (size_t)n * KP;
        float acc = 0.f;
        for (int k = 0; k < KP; k++) {
            float a = __bfloat162float(arh[k]) + __bfloat162float(arl[k]);
            float b = __bfloat162float(brh[k]) + __bfloat162float(brl[k]);
            acc = fmaf(a, b, acc);
        }
        size_t idx = m * (size_t)N + n;
        float v = alpha * acc;
        if (beta != 0.f) v = fmaf(beta, C[idx], v);
        C[idx] = v;
    }
#endif
}

// ---------------------------------------------------------------------------
// Elementwise / row kernels
// ---------------------------------------------------------------------------
__global__ void enc_kernel(const float* __restrict__ x,
                           const float* __restrict__ ew,
                           const float* __restrict__ eb,
                           float* __restrict__ H)
{
    size_t i = (size_t)blockIdx.x * blockDim.x + threadIdx.x;
    if (i >= MD) return;
    int d = (int)(i % DM);
    int m = (int)(i / DM);
    H[i] = fmaf(x[m], ew[d], eb[d]);
}

// fx = LN(LN(h,w1,b1),w2,b2), emitted as bf16 hi/lo [row, KP] (zero-padded)
__global__ __launch_bounds__(256) void ln2_kernel(
    const float* __restrict__ X,
    __nv_bfloat16* __restrict__ Oh, __nv_bfloat16* __restrict__ Ol,
    const float* __restrict__ w1, const float* __restrict__ b1,
    const float* __restrict__ w2, const float* __restrict__ b2)
{
    const int row = blockIdx.x;
    const int tid = threadIdx.x;
    const float* x = X + (size_t)row * DM;
    const size_t ro = (size_t)row * KP;
    __shared__ float sA[256], sB[256];

    float v[5];
    float s = 0.f, ss = 0.f;
    #pragma unroll
    for (int k = 0; k < 5; k++) {
        int d = tid + k * 256;
        float t = (d < DM) ? x[d] : 0.f;
        v[k] = t; s += t; ss += t * t;
    }
    sA[tid] = s; sB[tid] = ss; __syncthreads();
    for (int st = 128; st > 0; st >>= 1) {
        if (tid < st) { sA[tid] += sA[tid + st]; sB[tid] += sB[tid + st]; }
        __syncthreads();
    }
    float mu  = sA[0] * (1.0f / DM);
    float var = sB[0] * (1.0f / DM) - mu * mu;
    float rs  = rsqrtf(var + 1e-5f);
    __syncthreads();

    s = 0.f; ss = 0.f;
    #pragma unroll
    for (int k = 0; k < 5; k++) {
        int d = tid + k * 256;
        float r = 0.f;
        if (d < DM) r = fmaf((v[k] - mu) * rs, w1[d], b1[d]);
        v[k] = r; s += r; ss += r * r;
    }
    sA[tid] = s; sB[tid] = ss; __syncthreads();
    for (int st = 128; st > 0; st >>= 1) {
        if (tid < st) { sA[tid] += sA[tid + st]; sB[tid] += sB[tid + st]; }
        __syncthreads();
    }
    float mu2  = sA[0] * (1.0f / DM);
    float var2 = sB[0] * (1.0f / DM) - mu2 * mu2;
    float rs2  = rsqrtf(var2 + 1e-5f);
    #pragma unroll
    for (int k = 0; k < 5; k++) {
        int d = tid + k * 256;
        if (d < DM) {
            float r2 = fmaf((v[k] - mu2) * rs2, w2[d], b2[d]);
            __nv_bfloat16 h, l; split_bf16(r2, h, l);
            Oh[ro + d] = h; Ol[ro + d] = l;
        } else if (d < KP) {
            Oh[ro + d] = __float2bfloat16(0.f);
            Ol[ro + d] = __float2bfloat16(0.f);
        }
    }
}

// fy = LN(gelu(Y + Dvec*fx) + fx), fx reconstructed from bf16 hi/lo,
// output bf16 hi/lo [row, KP]
__global__ __launch_bounds__(256) void postln_kernel(
    const float* __restrict__ Y,
    const __nv_bfloat16* __restrict__ FXh, const __nv_bfloat16* __restrict__ FXl,
    const float* __restrict__ dv,
    const float* __restrict__ w, const float* __restrict__ b,
    __nv_bfloat16* __restrict__ Oh, __nv_bfloat16* __restrict__ Ol)
{
    const int row = blockIdx.x;
    const int tid = threadIdx.x;
    const float* y = Y + (size_t)row * DM;
    const size_t ro = (size_t)row * KP;
    __shared__ float sA[256], sB[256];

    float v[5];
    float s = 0.f, ss = 0.f;
    #pragma unroll
    for (int k = 0; k < 5; k++) {
        int d = tid + k * 256;
        float z = 0.f;
        if (d < DM) {
            float f = __bfloat162float(FXh[ro + d]) + __bfloat162float(FXl[ro + d]);
            float e = fmaf(dv[d], f, y[d]);
            z = gelu_exact(e) + f;
        }
        v[k] = z; s += z; ss += z * z;
    }
    sA[tid] = s; sB[tid] = ss; __syncthreads();
    for (int st = 128; st > 0; st >>= 1) {
        if (tid < st) { sA[tid] += sA[tid + st]; sB[tid] += sB[tid + st]; }
        __syncthreads();
    }
    float mu  = sA[0] * (1.0f / DM);
    float var = sB[0] * (1.0f / DM) - mu * mu;
    float rs  = rsqrtf(var + 1e-5f);
    #pragma unroll
    for (int k = 0; k < 5; k++) {
        int d = tid + k * 256;
        if (d < DM) {
            float r = fmaf((v[k] - mu) * rs, w[d], b[d]);
            __nv_bfloat16 h, l; split_bf16(r, h, l);
            Oh[ro + d] = h; Ol[ro + d] = l;
        } else if (d < KP) {
            Oh[ro + d] = __float2bfloat16(0.f);
            Ol[ro + d] = __float2bfloat16(0.f);
        }
    }
}

// Sequential ZOH scan per (b, p); writes xs as bf16 hi/lo planes [row, KP]
__global__ void scan_kernel(
    const float* __restrict__ GRE, const float* __restrict__ GIM,
    __nv_bfloat16* __restrict__ XRh, __nv_bfloat16* __restrict__ XRl,
    __nv_bfloat16* __restrict__ XIh, __nv_bfloat16* __restrict__ XIl,
    const float* __restrict__ lr_, const float* __restrict__ li_,
    const float* __restrict__ ls_)
{
    int t = blockIdx.x * blockDim.x + threadIdx.x;
    if (t >= BSZ * PD) return;
    int b = t / PD, p = t % PD;

    float lr = lr_[p], li = li_[p];
    float st = expf(ls_[p]);
    float er = expf(lr * st);
    float sn, cs; sincosf(li * st, &sn, &cs);
    float ar = er * cs, ai = er * sn;
    float inv = 1.0f / (lr * lr + li * li);
    float nr = ar - 1.0f;
    float cr = (nr * lr + ai * li) * inv;
    float ci = (ai * lr - nr * li) * inv;

    size_t goff = (size_t)b * LSEQ * PD + p;
    const float* gr = GRE + goff;
    const float* gi = GIM + goff;
    size_t ooff = (size_t)b * LSEQ * KP + p;

    float xr = 0.f, xi = 0.f;
    #pragma unroll 4
    for (int l = 0; l < LSEQ; l++) {
        float ur = gr[(size_t)l * PD];
        float ui = gi[(size_t)l * PD];
        float br = fmaf(cr, ur, -ci * ui);
        float bi = fmaf(cr, ui,  ci * ur);
        float nxr = fmaf(ar, xr, fmaf(-ai, xi, br));
        float nxi = fmaf(ar, xi, fmaf( ai, xr, bi));
        xr = nxr; xi = nxi;
        size_t o = ooff + (size_t)l * KP;
        __nv_bfloat16 h, lo;
        split_bf16(xr, h, lo); XRh[o] = h; XRl[o] = lo;
        split_bf16(xi, h, lo); XIh[o] = h; XIl[o] = lo;
    }
}

// zero pad columns [DM, KP) of the 4 scan-output planes (run once per launch)
__global__ void padscan_kernel(__nv_bfloat16* p0, __nv_bfloat16* p1,
                               __nv_bfloat16* p2, __nv_bfloat16* p3)
{
    int i = blockIdx.x * blockDim.x + threadIdx.x;
    const int PADW = KP - DM;
    if (i >= MROWS * PADW) return;
    int r = i / PADW, c = DM + i % PADW;
    size_t idx = (size_t)r * KP + c;
    __nv_bfloat16 z = __float2bfloat16(0.f);
    p0[idx] = z; p1[idx] = z; p2[idx] = z; p3[idx] = z;
}

// GEGLU: T[m,d] = H2[m,d] * gelu(H2[m,DM+d]) as bf16 hi/lo [m, KP]
__global__ void geglu_kernel(const float* __restrict__ H2,
                             __nv_bfloat16* __restrict__ Th,
                             __nv_bfloat16* __restrict__ Tl)
{
    size_t i = (size_t)blockIdx.x * blockDim.x + threadIdx.x;
    if (i >= (size_t)MROWS * KP) return;
    int d = (int)(i % KP);
    size_t m = i / KP;
    if (d < DM) {
        const float* r = H2 + m * (size_t)(2 * DM);
        float v = r[d] * gelu_exact(r[DM + d]);
        __nv_bfloat16 h, l; split_bf16(v, h, l);
        Th[i] = h; Tl[i] = l;
    } else {
        Th[i] = __float2bfloat16(0.f);
        Tl[i] = __float2bfloat16(0.f);
    }
}

// h += Z + fy (fy from bf16 hi/lo)
__global__ void addres_kernel(float* __restrict__ H, const float* __restrict__ Z,
                              const __nv_bfloat16* __restrict__ FYh,
                              const __nv_bfloat16* __restrict__ FYl)
{
    size_t i = (size_t)blockIdx.x * blockDim.x + threadIdx.x;
    if (i >= MD) return;
    int d = (int)(i % DM);
    size_t m = i / DM;
    size_t j = m * KP + d;
    H[i] += Z[i] + __bfloat162float(FYh[j]) + __bfloat162float(FYl[j]);
}

// weight fp32 [N, DM] -> bf16 hi/lo [Npad, KP] zero-padded
__global__ void convw_kernel(const float* __restrict__ W,
                             __nv_bfloat16* __restrict__ Wh,
                             __nv_bfloat16* __restrict__ Wl,
                             int N, int Npad)
{
    size_t i = (size_t)blockIdx.x * blockDim.x + threadIdx.x;
    if (i >= (size_t)Npad * KP) return;
    int n = (int)(i / KP), k = (int)(i % KP);
    float v = (n < N && k < DM) ? W[(size_t)n * DM + k] : 0.f;
    __nv_bfloat16 h, l; split_bf16(v, h, l);
    Wh[i] = h; Wl[i] = l;
}

__global__ void zero_kernel(float* __restrict__ P, int n)
{
    int i = blockIdx.x * blockDim.x + threadIdx.x;
    if (i < n) P[i] = 0.f;
}

#define POOL_CHUNKS 32
__global__ void pool_kernel(const float* __restrict__ H, float* __restrict__ POOL)
{
    int t = blockIdx.x * blockDim.x + threadIdx.x;
    if (t >= BSZ * DM) return;
    int b = t / DM, d = t % DM;
    const int CL = LSEQ / POOL_CHUNKS;
    int l0 = blockIdx.y * CL;
    const float* h = H + (size_t)b * LSEQ * DM + (size_t)l0 * DM + d;
    float s = 0.f;
    #pragma unroll 8
    for (int l = 0; l < CL; l++) s += h[(size_t)l * DM];
    atomicAdd(&POOL[t], s);
}

__global__ void head_kernel(const float* __restrict__ POOL,
                            const float* __restrict__ hw,
                            const float* __restrict__ hb,
                            float* __restrict__ out)
{
    int b = blockIdx.x;
    int tid = threadIdx.x;
    __shared__ float sA[256];
    float s = 0.f;
    for (int d = tid; d < DM; d += 256) s = fmaf(POOL[b * DM + d], hw[d], s);
    sA[tid] = s; __syncthreads();
    for (int st = 128; st > 0; st >>= 1) {
        if (tid < st) sA[tid] += sA[tid + st];
        __syncthreads();
    }
    if (tid == 0) out[b] = sA[0] * (1.0f / LSEQ) + hb[0];
}

// ---------------------------------------------------------------------------
// kernel_launch
// ---------------------------------------------------------------------------
extern "C" void kernel_launch(void* const* d_in, const int* in_sizes, int n_in,
                              void* d_out, int out_size)
{
    const float* x           = (const float*)d_in[0];
    const float* enc_w       = (const float*)d_in[1];
    const float* enc_b       = (const float*)d_in[2];
    const float* norm_w      = (const float*)d_in[3];
    const float* norm_b      = (const float*)d_in[4];
    const float* attn_norm_w = (const float*)d_in[5];
    const float* attn_norm_b = (const float*)d_in[6];
    const float* ff_norm_w   = (const float*)d_in[7];
    const float* ff_norm_b   = (const float*)d_in[8];
    const float* lam_re      = (const float*)d_in[9];
    const float* lam_im      = (const float*)d_in[10];
    const float* log_step    = (const float*)d_in[11];
    const float* B_re        = (const float*)d_in[12];
    const float* B_im        = (const float*)d_in[13];
    const float* C_re        = (const float*)d_in[14];
    const float* C_im        = (const float*)d_in[15];
    const float* Dvec        = (const float*)d_in[16];
    const float* Wenc        = (const float*)d_in[17];
    const float* Wdec        = (const float*)d_in[18];
    const float* head_w      = (const float*)d_in[19];
    const float* head_b      = (const float*)d_in[20];
    float* out = (float*)d_out;

    float* base = nullptr;
    cudaGetSymbolAddress((void**)&base, g_scratch);

    float* H    = base + OFF_H;
    float* GRE  = base + OFF_GRE;
    float* GIM  = base + OFF_GIM;
    float* Y    = base + OFF_Y;
    float* Z    = base + OFF_Z;
    float* H2   = base + OFF_H2;
    float* POOL = base + OFF_POOL;

    __nv_bfloat16* actb = (__nv_bfloat16*)(base + OFF_ACT);
    const size_t AE = (size_t)MROWS * KP;
    __nv_bfloat16* FXh = actb + 0 * AE;
    __nv_bfloat16* FXl = actb + 1 * AE;
    __nv_bfloat16* XRh = actb + 2 * AE;
    __nv_bfloat16* XRl = actb + 3 * AE;
    __nv_bfloat16* XIh = actb + 4 * AE;
    __nv_bfloat16* XIl = actb + 5 * AE;
    __nv_bfloat16* FYh = actb + 6 * AE;
    __nv_bfloat16* FYl = actb + 7 * AE;
    __nv_bfloat16* Th  = actb + 8 * AE;
    __nv_bfloat16* Tl  = actb + 9 * AE;

    __nv_bfloat16* wb = (__nv_bfloat16*)(base + OFF_WB);
    const size_t W1E = (size_t)NP1 * KP;   // 1,253,376
    const size_t W2E = (size_t)NP2 * KP;   // 2,367,488
    const size_t WLE = 10 * W1E + 2 * W2E;

    cudaFuncSetAttribute(gemm_bf16x3, cudaFuncAttributeMaxDynamicSharedMemorySize,
                         GEMM_SMEM_BYTES);

    const int EW_BLOCKS = (int)((MD + 255) / 256);

    enc_kernel<<<EW_BLOCKS, 256>>>(x, enc_w, enc_b, H);
    {
        int npad = MROWS * (KP - DM);
        padscan_kernel<<<(npad + 255) / 256, 256>>>(XRh, XRl, XIh, XIl);
    }

    // weight conversions
    for (int i = 0; i < NLAYERS; i++) {
        __nv_bfloat16* L = wb + (size_t)i * WLE;
        __nv_bfloat16* Breh = L;             __nv_bfloat16* Brel = L + 1*W1E;
        __nv_bfloat16* Bimh = L + 2*W1E;     __nv_bfloat16* Biml = L + 3*W1E;
        __nv_bfloat16* Creh = L + 4*W1E;     __nv_bfloat16* Crel = L + 5*W1E;
        __nv_bfloat16* Cimh = L + 6*W1E;     __nv_bfloat16* Ciml = L + 7*W1E;
        __nv_bfloat16* Wdh  = L + 8*W1E;     __nv_bfloat16* Wdl  = L + 9*W1E;
        __nv_bfloat16* Weh  = L + 10*W1E;    __nv_bfloat16* Wel  = L + 10*W1E + W2E;
        int g1 = (int)((W1E + 255) / 256), g2 = (int)((W2E + 255) / 256);
        convw_kernel<<<g1, 256>>>(B_re + (size_t)i*PD*DM, Breh, Brel, PD, NP1);
        convw_kernel<<<g1, 256>>>(B_im + (size_t)i*PD*DM, Bimh, Biml, PD, NP1);
        convw_kernel<<<g1, 256>>>(C_re + (size_t)i*DM*PD, Creh, Crel, DM, NP1);
        convw_kernel<<<g1, 256>>>(C_im + (size_t)i*DM*PD, Cimh, Ciml, DM, NP1);
        convw_kernel<<<g1, 256>>>(Wdec + (size_t)i*DM*DM, Wdh, Wdl, DM, NP1);
        convw_kernel<<<g2, 256>>>(Wenc + (size_t)i*2*DM*DM, Weh, Wel, 2*DM, NP2);
    }

    dim3 g9(NP1 / 128, MROWS / 128);   // N = 1048
    dim3 g17(NP2 / 128, MROWS / 128);  // N = 2096

    for (int i = 0; i < NLAYERS; i++) {
        const float* nw  = norm_w      + (size_t)i * DM;
        const float* nb  = norm_b      + (size_t)i * DM;
        const float* aw  = attn_norm_w + (size_t)i * DM;
        const float* ab  = attn_norm_b + (size_t)i * DM;
        const float* fw  = ff_norm_w   + (size_t)i * DM;
        const float* fb  = ff_norm_b   + (size_t)i * DM;
        const float* lre = lam_re      + (size_t)i * PD;
        const float* lim = lam_im      + (size_t)i * PD;
        const float* lst = log_step    + (size_t)i * PD;
        const float* dv  = Dvec        + (size_t)i * DM;

        __nv_bfloat16* L = wb + (size_t)i * WLE;
        __nv_bfloat16* Breh = L;             __nv_bfloat16* Brel = L + 1*W1E;
        __nv_bfloat16* Bimh = L + 2*W1E;     __nv_bfloat16* Biml = L + 3*W1E;
        __nv_bfloat16* Creh = L + 4*W1E;     __nv_bfloat16* Crel = L + 5*W1E;
        __nv_bfloat16* Cimh = L + 6*W1E;     __nv_bfloat16* Ciml = L + 7*W1E;
        __nv_bfloat16* Wdh  = L + 8*W1E;     __nv_bfloat16* Wdl  = L + 9*W1E;
        __nv_bfloat16* Weh  = L + 10*W1E;    __nv_bfloat16* Wel  = L + 10*W1E + W2E;

        ln2_kernel<<<MROWS, 256>>>(H, FXh, FXl, nw, nb, aw, ab);

        gemm_bf16x3<<<g9, 128, GEMM_SMEM_BYTES>>>(FXh, FXl, Breh, Brel, GRE, PD, 1.f, 0.f);
        gemm_bf16x3<<<g9, 128, GEMM_SMEM_BYTES>>>(FXh, FXl, Bimh, Biml, GIM, PD, 1.f, 0.f);

        scan_kernel<<<(BSZ * PD + 127) / 128, 128>>>(GRE, GIM, XRh, XRl, XIh, XIl,
                                                     lre, lim, lst);

        gemm_bf16x3<<<g9, 128, GEMM_SMEM_BYTES>>>(XRh, XRl, Creh, Crel, Y, DM, 1.f, 0.f);
        gemm_bf16x3<<<g9, 128, GEMM_SMEM_BYTES>>>(XIh, XIl, Cimh, Ciml, Y, DM, -1.f, 1.f);

        postln_kernel<<<MROWS, 256>>>(Y, FXh, FXl, dv, fw, fb, FYh, FYl);

        gemm_bf16x3<<<g17, 128, GEMM_SMEM_BYTES>>>(FYh, FYl, Weh, Wel, H2, 2 * DM, 1.f, 0.f);

        {
            size_t n = (size_t)MROWS * KP;
            geglu_kernel<<<(int)((n + 255) / 256), 256>>>(H2, Th, Tl);
        }

        gemm_bf16x3<<<g9, 128, GEMM_SMEM_BYTES>>>(Th, Tl, Wdh, Wdl, Z, DM, 1.f, 0.f);

        addres_kernel<<<EW_BLOCKS, 256>>>(H, Z, FYh, FYl);
    }

    zero_kernel<<<(BSZ * DM + 255) / 256, 256>>>(POOL, BSZ * DM);
    dim3 gp((BSZ * DM + 127) / 128, POOL_CHUNKS);
    pool_kernel<<<gp, 128>>>(H, POOL);
    head_kernel<<<BSZ, 256>>>(POOL, head_w, head_b, out);
}

// round 5
// speedup vs baseline: 1.6993x; 1.6348x over previous
#include <cuda_runtime.h>
#include <cuda_bf16.h>
#include <math.h>
#include <cstdint>

// ---------------------------------------------------------------------------
// Problem constants
// ---------------------------------------------------------------------------
#define BSZ     4
#define LSEQ    4096
#define DM      1048
#define PD      1048
#define NLAYERS 3
#define MROWS   (BSZ*LSEQ)              // 16384
#define MD      ((size_t)MROWS * DM)    // 17,170,432
#define KP      1088                    // K padded to multiple of 32
#define NCHUNK  (KP/32)                 // 34
#define NP1     1152                    // 1048 padded to 128 (9 tiles)
#define NP2     2176                    // 2096 padded to 128 (17 tiles)

// sizes in floats
#define MD_F   17170432ULL
#define ACT_F  8912896ULL               // (16384*1088 bf16)/2
#define W1_F   626688ULL                // (1152*1088 bf16)/2
#define W2_F   1183744ULL               // (2176*1088 bf16)/2
#define WL_F   (10ULL*W1_F + 2ULL*W2_F)

#define OFF_H    0ULL
#define OFF_GRE  (1ULL*MD_F)
#define OFF_GIM  (2ULL*MD_F)
#define OFF_Y    (3ULL*MD_F)
#define OFF_Z    (4ULL*MD_F)
#define OFF_H2   (5ULL*MD_F)
#define OFF_ACT  (7ULL*MD_F)
#define OFF_WB   (OFF_ACT + 10ULL*ACT_F)
#define OFF_POOL (OFF_WB + 3ULL*WL_F)
#define TOT_F    (OFF_POOL + 8192ULL)

__device__ __align__(1024) float g_scratch[TOT_F];

__device__ __forceinline__ float gelu_exact(float x) {
    return 0.5f * x * (1.0f + erff(x * 0.70710678118654752f));
}

__device__ __forceinline__ uint32_t smem_u32_of(const void* p) {
    uint32_t a;
    asm("{ .reg .u64 t; cvta.to.shared.u64 t, %1; cvt.u32.u64 %0, t; }"
        : "=r"(a) : "l"(p));
    return a;
}

__device__ __forceinline__ void split_bf16(float v, __nv_bfloat16& h, __nv_bfloat16& l) {
    h = __float2bfloat16(v);
    l = __float2bfloat16(v - __bfloat162float(h));
}

// ---------------------------------------------------------------------------
// Portable tensor-core GEMM (mma.sync m16n8k16 bf16, valid on base sm_103):
// C[M,N] = alpha * (Ah+Al)[M,KP] @ (Bh+Bl)[N,KP]^T + beta*C   (3-term split)
// 128x128 CTA tile, BK=32, 8 warps each 64x32, cp.async double buffer.
// Grid: (Npad/128, M/128), 256 threads.
// ---------------------------------------------------------------------------
#define ROWB    80                    // smem row stride bytes (32 bf16 + 8 pad)
#define PLANEB  (128*ROWB)            // 10240
#define STAGEB  (4*PLANEB)            // 40960
#define GEMM_SMEM_BYTES (2*STAGEB)    // 81920

#define CP_ASYNC_16(saddr, gptr) \
    asm volatile("cp.async.cg.shared.global [%0], [%1], 16;" \
        :: "r"(saddr), "l"(gptr) : "memory")
#define CP_COMMIT() asm volatile("cp.async.commit_group;" ::: "memory")
#define CP_WAIT_1() asm volatile("cp.async.wait_group 1;" ::: "memory")

#define LDMATRIX_X4(r0, r1, r2, r3, addr) \
    asm volatile("ldmatrix.sync.aligned.m8n8.x4.shared.b16 {%0,%1,%2,%3}, [%4];" \
        : "=r"(r0), "=r"(r1), "=r"(r2), "=r"(r3) : "r"(addr))

#define MMA_BF16(c, a, b0, b1) \
    asm volatile("mma.sync.aligned.m16n8k16.row.col.f32.bf16.bf16.f32 " \
        "{%0,%1,%2,%3},{%4,%5,%6,%7},{%8,%9},{%0,%1,%2,%3};" \
        : "+f"((c)[0]), "+f"((c)[1]), "+f"((c)[2]), "+f"((c)[3]) \
        : "r"((a)[0]), "r"((a)[1]), "r"((a)[2]), "r"((a)[3]), "r"(b0), "r"(b1))

__global__ __launch_bounds__(256) void gemm_bf16x3(
    const __nv_bfloat16* __restrict__ Ah, const __nv_bfloat16* __restrict__ Al,
    const __nv_bfloat16* __restrict__ Bh, const __nv_bfloat16* __restrict__ Bl,
    float* __restrict__ C, int N, float alpha, float beta)
{
    extern __shared__ __align__(128) char smem[];
    const uint32_t sbase = smem_u32_of(smem);
    const int tid = threadIdx.x;
    const int wid = tid >> 5;
    const int lid = tid & 31;
    const int wm  = wid & 1;      // 2 warps in M
    const int wn  = wid >> 1;     // 4 warps in N

    const __nv_bfloat16* srcs[4];
    srcs[0] = Ah + (size_t)blockIdx.y * 128 * KP;
    srcs[1] = Al + (size_t)blockIdx.y * 128 * KP;
    srcs[2] = Bh + (size_t)blockIdx.x * 128 * KP;
    srcs[3] = Bl + (size_t)blockIdx.x * 128 * KP;

    // per-thread prefetch coords: 512 16B-chunks per plane / 256 threads = 2
    const int c0row = (tid * 2) >> 2, c0col = (tid * 2) & 3;
    const int c1row = (tid * 2 + 1) >> 2, c1col = (tid * 2 + 1) & 3;

    auto prefetch = [&](int kc, int stage) {
        const int k0 = kc * 32;
        const uint32_t stb = sbase + stage * STAGEB;
        #pragma unroll
        for (int pl = 0; pl < 4; pl++) {
            const __nv_bfloat16* src = srcs[pl];
            uint32_t pb = stb + pl * PLANEB;
            CP_ASYNC_16(pb + c0row * ROWB + c0col * 16,
                        src + (size_t)c0row * KP + k0 + c0col * 8);
            CP_ASYNC_16(pb + c1row * ROWB + c1col * 16,
                        src + (size_t)c1row * KP + k0 + c1col * 8);
        }
    };

    float acc[4][4][4];
    #pragma unroll
    for (int i = 0; i < 4; i++)
        #pragma unroll
        for (int j = 0; j < 4; j++)
            #pragma unroll
            for (int k = 0; k < 4; k++) acc[i][j][k] = 0.f;

    prefetch(0, 0);
    CP_COMMIT();

    // ldmatrix lane address components (same pattern for A and B)
    const int lrow = lid & 15;
    const int lcol = (lid >> 4) << 4;   // 0 or 16 bytes

    for (int kc = 0; kc < NCHUNK; kc++) {
        if (kc + 1 < NCHUNK) prefetch(kc + 1, (kc + 1) & 1);
        CP_COMMIT();
        CP_WAIT_1();
        __syncthreads();

        const uint32_t stb = sbase + (kc & 1) * STAGEB;
        const uint32_t aHb = stb;
        const uint32_t aLb = stb + PLANEB;
        const uint32_t bHb = stb + 2 * PLANEB;
        const uint32_t bLb = stb + 3 * PLANEB;

        #pragma unroll
        for (int ks = 0; ks < 2; ks++) {
            uint32_t ah[4][4], al[4][4], bh[2][4], bl[2][4];
            #pragma unroll
            for (int mb = 0; mb < 4; mb++) {
                uint32_t off = (uint32_t)((wm * 64 + mb * 16 + lrow) * ROWB + ks * 32 + lcol);
                LDMATRIX_X4(ah[mb][0], ah[mb][1], ah[mb][2], ah[mb][3], aHb + off);
                LDMATRIX_X4(al[mb][0], al[mb][1], al[mb][2], al[mb][3], aLb + off);
            }
            #pragma unroll
            for (int p = 0; p < 2; p++) {
                uint32_t off = (uint32_t)((wn * 32 + p * 16 + lrow) * ROWB + ks * 32 + lcol);
                LDMATRIX_X4(bh[p][0], bh[p][1], bh[p][2], bh[p][3], bHb + off);
                LDMATRIX_X4(bl[p][0], bl[p][1], bl[p][2], bl[p][3], bLb + off);
            }
            // With this addressing, ldmatrix x4 register order for B is:
            //   r0 = n(0-7)/k(0-7), r1 = n(8-15)/k(0-7),
            //   r2 = n(0-7)/k(8-15), r3 = n(8-15)/k(8-15)
            // mma B operand (b0,b1) must be (k0-7, k8-15) of the SAME n-octet:
            //   n-octet 0 -> (r0, r2), n-octet 1 -> (r1, r3).
            #pragma unroll
            for (int mb = 0; mb < 4; mb++) {
                #pragma unroll
                for (int nb = 0; nb < 4; nb++) {
                    uint32_t b0h = bh[nb >> 1][(nb & 1)];
                    uint32_t b1h = bh[nb >> 1][(nb & 1) + 2];
                    uint32_t b0l = bl[nb >> 1][(nb & 1)];
                    uint32_t b1l = bl[nb >> 1][(nb & 1) + 2];
                    MMA_BF16(acc[mb][nb], ah[mb], b0h, b1h);
                    MMA_BF16(acc[mb][nb], ah[mb], b0l, b1l);
                    MMA_BF16(acc[mb][nb], al[mb], b0h, b1h);
                }
            }
        }
        __syncthreads();
    }

    // epilogue: registers -> gmem
    const int tig = lid & 3;
    const int grp = lid >> 2;
    const int mBase = blockIdx.y * 128 + wm * 64;
    const int nBase = blockIdx.x * 128 + wn * 32;
    #pragma unroll
    for (int mb = 0; mb < 4; mb++) {
        #pragma unroll
        for (int nb = 0; nb < 4; nb++) {
            int n = nBase + nb * 8 + tig * 2;
            if (n >= N) continue;   // N is even -> n+1 < N too
            int m0 = mBase + mb * 16 + grp;
            size_t i0 = (size_t)m0 * N + n;
            size_t i1 = (size_t)(m0 + 8) * N + n;
            float v0 = alpha * acc[mb][nb][0];
            float v1 = alpha * acc[mb][nb][1];
            float v2 = alpha * acc[mb][nb][2];
            float v3 = alpha * acc[mb][nb][3];
            if (beta != 0.f) {
                v0 = fmaf(beta, C[i0], v0);
                v1 = fmaf(beta, C[i0 + 1], v1);
                v2 = fmaf(beta, C[i1], v2);
                v3 = fmaf(beta, C[i1 + 1], v3);
            }
            *reinterpret_cast<float2*>(C + i0) = make_float2(v0, v1);
            *reinterpret_cast<float2*>(C + i1) = make_float2(v2, v3);
        }
    }
}

// ---------------------------------------------------------------------------
// Elementwise / row kernels
// ---------------------------------------------------------------------------
__global__ void enc_kernel(const float* __restrict__ x,
                           const float* __restrict__ ew,
                           const float* __restrict__ eb,
                           float* __restrict__ H)
{
    size_t i = (size_t)blockIdx.x * blockDim.x + threadIdx.x;
    if (i >= MD) return;
    int d = (int)(i % DM);
    int m = (int)(i / DM);
    H[i] = fmaf(x[m], ew[d], eb[d]);
}

// fx = LN(LN(h,w1,b1),w2,b2), emitted as bf16 hi/lo [row, KP] (zero-padded)
__global__ __launch_bounds__(256) void ln2_kernel(
    const float* __restrict__ X,
    __nv_bfloat16* __restrict__ Oh, __nv_bfloat16* __restrict__ Ol,
    const float* __restrict__ w1, const float* __restrict__ b1,
    const float* __restrict__ w2, const float* __restrict__ b2)
{
    const int row = blockIdx.x;
    const int tid = threadIdx.x;
    const float* x = X + (size_t)row * DM;
    const size_t ro = (size_t)row * KP;
    __shared__ float sA[256], sB[256];

    float v[5];
    float s = 0.f, ss = 0.f;
    #pragma unroll
    for (int k = 0; k < 5; k++) {
        int d = tid + k * 256;
        float t = (d < DM) ? x[d] : 0.f;
        v[k] = t; s += t; ss += t * t;
    }
    sA[tid] = s; sB[tid] = ss; __syncthreads();
    for (int st = 128; st > 0; st >>= 1) {
        if (tid < st) { sA[tid] += sA[tid + st]; sB[tid] += sB[tid + st]; }
        __syncthreads();
    }
    float mu  = sA[0] * (1.0f / DM);
    float var = sB[0] * (1.0f / DM) - mu * mu;
    float rs  = rsqrtf(var + 1e-5f);
    __syncthreads();

    s = 0.f; ss = 0.f;
    #pragma unroll
    for (int k = 0; k < 5; k++) {
        int d = tid + k * 256;
        float r = 0.f;
        if (d < DM) r = fmaf((v[k] - mu) * rs, w1[d], b1[d]);
        v[k] = r; s += r; ss += r * r;
    }
    sA[tid] = s; sB[tid] = ss; __syncthreads();
    for (int st = 128; st > 0; st >>= 1) {
        if (tid < st) { sA[tid] += sA[tid + st]; sB[tid] += sB[tid + st]; }
        __syncthreads();
    }
    float mu2  = sA[0] * (1.0f / DM);
    float var2 = sB[0] * (1.0f / DM) - mu2 * mu2;
    float rs2  = rsqrtf(var2 + 1e-5f);
    #pragma unroll
    for (int k = 0; k < 5; k++) {
        int d = tid + k * 256;
        if (d < DM) {
            float r2 = fmaf((v[k] - mu2) * rs2, w2[d], b2[d]);
            __nv_bfloat16 h, l; split_bf16(r2, h, l);
            Oh[ro + d] = h; Ol[ro + d] = l;
        } else if (d < KP) {
            Oh[ro + d] = __float2bfloat16(0.f);
            Ol[ro + d] = __float2bfloat16(0.f);
        }
    }
}

// fy = LN(gelu(Y + Dvec*fx) + fx)
__global__ __launch_bounds__(256) void postln_kernel(
    const float* __restrict__ Y,
    const __nv_bfloat16* __restrict__ FXh, const __nv_bfloat16* __restrict__ FXl,
    const float* __restrict__ dv,
    const float* __restrict__ w, const float* __restrict__ b,
    __nv_bfloat16* __restrict__ Oh, __nv_bfloat16* __restrict__ Ol)
{
    const int row = blockIdx.x;
    const int tid = threadIdx.x;
    const float* y = Y + (size_t)row * DM;
    const size_t ro = (size_t)row * KP;
    __shared__ float sA[256], sB[256];

    float v[5];
    float s = 0.f, ss = 0.f;
    #pragma unroll
    for (int k = 0; k < 5; k++) {
        int d = tid + k * 256;
        float z = 0.f;
        if (d < DM) {
            float f = __bfloat162float(FXh[ro + d]) + __bfloat162float(FXl[ro + d]);
            float e = fmaf(dv[d], f, y[d]);
            z = gelu_exact(e) + f;
        }
        v[k] = z; s += z; ss += z * z;
    }
    sA[tid] = s; sB[tid] = ss; __syncthreads();
    for (int st = 128; st > 0; st >>= 1) {
        if (tid < st) { sA[tid] += sA[tid + st]; sB[tid] += sB[tid + st]; }
        __syncthreads();
    }
    float mu  = sA[0] * (1.0f / DM);
    float var = sB[0] * (1.0f / DM) - mu * mu;
    float rs  = rsqrtf(var + 1e-5f);
    #pragma unroll
    for (int k = 0; k < 5; k++) {
        int d = tid + k * 256;
        if (d < DM) {
            float r = fmaf((v[k] - mu) * rs, w[d], b[d]);
            __nv_bfloat16 h, l; split_bf16(r, h, l);
            Oh[ro + d] = h; Ol[ro + d] = l;
        } else if (d < KP) {
            Oh[ro + d] = __float2bfloat16(0.f);
            Ol[ro + d] = __float2bfloat16(0.f);
        }
    }
}

// Sequential ZOH scan per (b, p); writes xs as bf16 hi/lo planes [row, KP]
__global__ void scan_kernel(
    const float* __restrict__ GRE, const float* __restrict__ GIM,
    __nv_bfloat16* __restrict__ XRh, __nv_bfloat16* __restrict__ XRl,
    __nv_bfloat16* __restrict__ XIh, __nv_bfloat16* __restrict__ XIl,
    const float* __restrict__ lr_, const float* __restrict__ li_,
    const float* __restrict__ ls_)
{
    int t = blockIdx.x * blockDim.x + threadIdx.x;
    if (t >= BSZ * PD) return;
    int b = t / PD, p = t % PD;

    float lr = lr_[p], li = li_[p];
    float st = expf(ls_[p]);
    float er = expf(lr * st);
    float sn, cs; sincosf(li * st, &sn, &cs);
    float ar = er * cs, ai = er * sn;
    float inv = 1.0f / (lr * lr + li * li);
    float nr = ar - 1.0f;
    float cr = (nr * lr + ai * li) * inv;
    float ci = (ai * lr - nr * li) * inv;

    size_t goff = (size_t)b * LSEQ * PD + p;
    const float* gr = GRE + goff;
    const float* gi = GIM + goff;
    size_t ooff = (size_t)b * LSEQ * KP + p;

    float xr = 0.f, xi = 0.f;
    #pragma unroll 4
    for (int l = 0; l < LSEQ; l++) {
        float ur = gr[(size_t)l * PD];
        float ui = gi[(size_t)l * PD];
        float br = fmaf(cr, ur, -ci * ui);
        float bi = fmaf(cr, ui,  ci * ur);
        float nxr = fmaf(ar, xr, fmaf(-ai, xi, br));
        float nxi = fmaf(ar, xi, fmaf( ai, xr, bi));
        xr = nxr; xi = nxi;
        size_t o = ooff + (size_t)l * KP;
        __nv_bfloat16 h, lo;
        split_bf16(xr, h, lo); XRh[o] = h; XRl[o] = lo;
        split_bf16(xi, h, lo); XIh[o] = h; XIl[o] = lo;
    }
}

// zero pad columns [DM, KP) of the 4 scan-output planes
__global__ void padscan_kernel(__nv_bfloat16* p0, __nv_bfloat16* p1,
                               __nv_bfloat16* p2, __nv_bfloat16* p3)
{
    int i = blockIdx.x * blockDim.x + threadIdx.x;
    const int PADW = KP - DM;
    if (i >= MROWS * PADW) return;
    int r = i / PADW, c = DM + i % PADW;
    size_t idx = (size_t)r * KP + c;
    __nv_bfloat16 z = __float2bfloat16(0.f);
    p0[idx] = z; p1[idx] = z; p2[idx] = z; p3[idx] = z;
}

// GEGLU: T[m,d] = H2[m,d] * gelu(H2[m,DM+d]) as bf16 hi/lo [m, KP]
__global__ void geglu_kernel(const float* __restrict__ H2,
                             __nv_bfloat16* __restrict__ Th,
                             __nv_bfloat16* __restrict__ Tl)
{
    size_t i = (size_t)blockIdx.x * blockDim.x + threadIdx.x;
    if (i >= (size_t)MROWS * KP) return;
    int d = (int)(i % KP);
    size_t m = i / KP;
    if (d < DM) {
        const float* r = H2 + m * (size_t)(2 * DM);
        float v = r[d] * gelu_exact(r[DM + d]);
        __nv_bfloat16 h, l; split_bf16(v, h, l);
        Th[i] = h; Tl[i] = l;
    } else {
        Th[i] = __float2bfloat16(0.f);
        Tl[i] = __float2bfloat16(0.f);
    }
}

// h += Z + fy
__global__ void addres_kernel(float* __restrict__ H, const float* __restrict__ Z,
                              const __nv_bfloat16* __restrict__ FYh,
                              const __nv_bfloat16* __restrict__ FYl)
{
    size_t i = (size_t)blockIdx.x * blockDim.x + threadIdx.x;
    if (i >= MD) return;
    int d = (int)(i % DM);
    size_t m = i / DM;
    size_t j = m * KP + d;
    H[i] += Z[i] + __bfloat162float(FYh[j]) + __bfloat162float(FYl[j]);
}

// weight fp32 [N, DM] -> bf16 hi/lo [Npad, KP] zero-padded
__global__ void convw_kernel(const float* __restrict__ W,
                             __nv_bfloat16* __restrict__ Wh,
                             __nv_bfloat16* __restrict__ Wl,
                             int N, int Npad)
{
    size_t i = (size_t)blockIdx.x * blockDim.x + threadIdx.x;
    if (i >= (size_t)Npad * KP) return;
    int n = (int)(i / KP), k = (int)(i % KP);
    float v = (n < N && k < DM) ? W[(size_t)n * DM + k] : 0.f;
    __nv_bfloat16 h, l; split_bf16(v, h, l);
    Wh[i] = h; Wl[i] = l;
}

__global__ void zero_kernel(float* __restrict__ P, int n)
{
    int i = blockIdx.x * blockDim.x + threadIdx.x;
    if (i < n) P[i] = 0.f;
}

#define POOL_CHUNKS 32
__global__ void pool_kernel(const float* __restrict__ H, float* __restrict__ POOL)
{
    int t = blockIdx.x * blockDim.x + threadIdx.x;
    if (t >= BSZ * DM) return;
    int b = t / DM, d = t % DM;
    const int CL = LSEQ / POOL_CHUNKS;
    int l0 = blockIdx.y * CL;
    const float* h = H + (size_t)b * LSEQ * DM + (size_t)l0 * DM + d;
    float s = 0.f;
    #pragma unroll 8
    for (int l = 0; l < CL; l++) s += h[(size_t)l * DM];
    atomicAdd(&POOL[t], s);
}

__global__ void head_kernel(const float* __restrict__ POOL,
                            const float* __restrict__ hw,
                            const float* __restrict__ hb,
                            float* __restrict__ out)
{
    int b = blockIdx.x;
    int tid = threadIdx.x;
    __shared__ float sA[256];
    float s = 0.f;
    for (int d = tid; d < DM; d += 256) s = fmaf(POOL[b * DM + d], hw[d], s);
    sA[tid] = s; __syncthreads();
    for (int st = 128; st > 0; st >>= 1) {
        if (tid < st) sA[tid] += sA[tid + st];
        __syncthreads();
    }
    if (tid == 0) out[b] = sA[0] * (1.0f / LSEQ) + hb[0];
}

// ---------------------------------------------------------------------------
// kernel_launch
// ---------------------------------------------------------------------------
extern "C" void kernel_launch(void* const* d_in, const int* in_sizes, int n_in,
                              void* d_out, int out_size)
{
    const float* x           = (const float*)d_in[0];
    const float* enc_w       = (const float*)d_in[1];
    const float* enc_b       = (const float*)d_in[2];
    const float* norm_w      = (const float*)d_in[3];
    const float* norm_b      = (const float*)d_in[4];
    const float* attn_norm_w = (const float*)d_in[5];
    const float* attn_norm_b = (const float*)d_in[6];
    const float* ff_norm_w   = (const float*)d_in[7];
    const float* ff_norm_b   = (const float*)d_in[8];
    const float* lam_re      = (const float*)d_in[9];
    const float* lam_im      = (const float*)d_in[10];
    const float* log_step    = (const float*)d_in[11];
    const float* B_re        = (const float*)d_in[12];
    const float* B_im        = (const float*)d_in[13];
    const float* C_re        = (const float*)d_in[14];
    const float* C_im        = (const float*)d_in[15];
    const float* Dvec        = (const float*)d_in[16];
    const float* Wenc        = (const float*)d_in[17];
    const float* Wdec        = (const float*)d_in[18];
    const float* head_w      = (const float*)d_in[19];
    const float* head_b      = (const float*)d_in[20];
    float* out = (float*)d_out;

    float* base = nullptr;
    cudaGetSymbolAddress((void**)&base, g_scratch);

    float* H    = base + OFF_H;
    float* GRE  = base + OFF_GRE;
    float* GIM  = base + OFF_GIM;
    float* Y    = base + OFF_Y;
    float* Z    = base + OFF_Z;
    float* H2   = base + OFF_H2;
    float* POOL = base + OFF_POOL;

    __nv_bfloat16* actb = (__nv_bfloat16*)(base + OFF_ACT);
    const size_t AE = (size_t)MROWS * KP;
    __nv_bfloat16* FXh = actb + 0 * AE;
    __nv_bfloat16* FXl = actb + 1 * AE;
    __nv_bfloat16* XRh = actb + 2 * AE;
    __nv_bfloat16* XRl = actb + 3 * AE;
    __nv_bfloat16* XIh = actb + 4 * AE;
    __nv_bfloat16* XIl = actb + 5 * AE;
    __nv_bfloat16* FYh = actb + 6 * AE;
    __nv_bfloat16* FYl = actb + 7 * AE;
    __nv_bfloat16* Th  = actb + 8 * AE;
    __nv_bfloat16* Tl  = actb + 9 * AE;

    __nv_bfloat16* wb = (__nv_bfloat16*)(base + OFF_WB);
    const size_t W1E = (size_t)NP1 * KP;
    const size_t W2E = (size_t)NP2 * KP;
    const size_t WLE = 10 * W1E + 2 * W2E;

    cudaFuncSetAttribute(gemm_bf16x3, cudaFuncAttributeMaxDynamicSharedMemorySize,
                         GEMM_SMEM_BYTES);

    const int EW_BLOCKS = (int)((MD + 255) / 256);

    enc_kernel<<<EW_BLOCKS, 256>>>(x, enc_w, enc_b, H);
    {
        int npad = MROWS * (KP - DM);
        padscan_kernel<<<(npad + 255) / 256, 256>>>(XRh, XRl, XIh, XIl);
    }

    // weight conversions
    for (int i = 0; i < NLAYERS; i++) {
        __nv_bfloat16* L = wb + (size_t)i * WLE;
        __nv_bfloat16* Breh = L;             __nv_bfloat16* Brel = L + 1*W1E;
        __nv_bfloat16* Bimh = L + 2*W1E;     __nv_bfloat16* Biml = L + 3*W1E;
        __nv_bfloat16* Creh = L + 4*W1E;     __nv_bfloat16* Crel = L + 5*W1E;
        __nv_bfloat16* Cimh = L + 6*W1E;     __nv_bfloat16* Ciml = L + 7*W1E;
        __nv_bfloat16* Wdh  = L + 8*W1E;     __nv_bfloat16* Wdl  = L + 9*W1E;
        __nv_bfloat16* Weh  = L + 10*W1E;    __nv_bfloat16* Wel  = L + 10*W1E + W2E;
        int g1 = (int)((W1E + 255) / 256), g2 = (int)((W2E + 255) / 256);
        convw_kernel<<<g1, 256>>>(B_re + (size_t)i*PD*DM, Breh, Brel, PD, NP1);
        convw_kernel<<<g1, 256>>>(B_im + (size_t)i*PD*DM, Bimh, Biml, PD, NP1);
        convw_kernel<<<g1, 256>>>(C_re + (size_t)i*DM*PD, Creh, Crel, DM, NP1);
        convw_kernel<<<g1, 256>>>(C_im + (size_t)i*DM*PD, Cimh, Ciml, DM, NP1);
        convw_kernel<<<g1, 256>>>(Wdec + (size_t)i*DM*DM, Wdh, Wdl, DM, NP1);
        convw_kernel<<<g2, 256>>>(Wenc + (size_t)i*2*DM*DM, Weh, Wel, 2*DM, NP2);
    }

    dim3 g9(NP1 / 128, MROWS / 128);
    dim3 g17(NP2 / 128, MROWS / 128);

    for (int i = 0; i < NLAYERS; i++) {
        const float* nw  = norm_w      + (size_t)i * DM;
        const float* nb  = norm_b      + (size_t)i * DM;
        const float* aw  = attn_norm_w + (size_t)i * DM;
        const float* ab  = attn_norm_b + (size_t)i * DM;
        const float* fw  = ff_norm_w   + (size_t)i * DM;
        const float* fb  = ff_norm_b   + (size_t)i * DM;
        const float* lre = lam_re      + (size_t)i * PD;
        const float* lim = lam_im      + (size_t)i * PD;
        const float* lst = log_step    + (size_t)i * PD;
        const float* dv  = Dvec        + (size_t)i * DM;

        __nv_bfloat16* L = wb + (size_t)i * WLE;
        __nv_bfloat16* Breh = L;             __nv_bfloat16* Brel = L + 1*W1E;
        __nv_bfloat16* Bimh = L + 2*W1E;     __nv_bfloat16* Biml = L + 3*W1E;
        __nv_bfloat16* Creh = L + 4*W1E;     __nv_bfloat16* Crel = L + 5*W1E;
        __nv_bfloat16* Cimh = L + 6*W1E;     __nv_bfloat16* Ciml = L + 7*W1E;
        __nv_bfloat16* Wdh  = L + 8*W1E;     __nv_bfloat16* Wdl  = L + 9*W1E;
        __nv_bfloat16* Weh  = L + 10*W1E;    __nv_bfloat16* Wel  = L + 10*W1E + W2E;

        ln2_kernel<<<MROWS, 256>>>(H, FXh, FXl, nw, nb, aw, ab);

        gemm_bf16x3<<<g9, 256, GEMM_SMEM_BYTES>>>(FXh, FXl, Breh, Brel, GRE, PD, 1.f, 0.f);
        gemm_bf16x3<<<g9, 256, GEMM_SMEM_BYTES>>>(FXh, FXl, Bimh, Biml, GIM, PD, 1.f, 0.f);

        scan_kernel<<<(BSZ * PD + 127) / 128, 128>>>(GRE, GIM, XRh, XRl, XIh, XIl,
                                                     lre, lim, lst);

        gemm_bf16x3<<<g9, 256, GEMM_SMEM_BYTES>>>(XRh, XRl, Creh, Crel, Y, DM, 1.f, 0.f);
        gemm_bf16x3<<<g9, 256, GEMM_SMEM_BYTES>>>(XIh, XIl, Cimh, Ciml, Y, DM, -1.f, 1.f);

        postln_kernel<<<MROWS, 256>>>(Y, FXh, FXl, dv, fw, fb, FYh, FYl);

        gemm_bf16x3<<<g17, 256, GEMM_SMEM_BYTES>>>(FYh, FYl, Weh, Wel, H2, 2 * DM, 1.f, 0.f);

        {
            size_t n = (size_t)MROWS * KP;
            geglu_kernel<<<(int)((n + 255) / 256), 256>>>(H2, Th, Tl);
        }

        gemm_bf16x3<<<g9, 256, GEMM_SMEM_BYTES>>>(Th, Tl, Wdh, Wdl, Z, DM, 1.f, 0.f);

        addres_kernel<<<EW_BLOCKS, 256>>>(H, Z, FYh, FYl);
    }

    zero_kernel<<<(BSZ * DM + 255) / 256, 256>>>(POOL, BSZ * DM);
    dim3 gp((BSZ * DM + 127) / 128, POOL_CHUNKS);
    pool_kernel<<<gp, 128>>>(H, POOL);
    head_kernel<<<BSZ, 256>>>(POOL, head_w, head_b, out);
}

// round 6
// speedup vs baseline: 1.7740x; 1.0439x over previous
#include <cuda_runtime.h>
#include <cuda_bf16.h>
#include <math.h>
#include <cstdint>

// ---------------------------------------------------------------------------
// Problem constants
// ---------------------------------------------------------------------------
#define BSZ     4
#define LSEQ    4096
#define DM      1048
#define PD      1048
#define NLAYERS 3
#define MROWS   (BSZ*LSEQ)              // 16384
#define MD      ((size_t)MROWS * DM)    // 17,170,432
#define KP      1088                    // K padded to multiple of 64
#define NCHUNK  (KP/64)                 // 17 (BK=64)
#define NP1     1152
#define NP2     2176

#define MD_F   17170432ULL
#define ACT_F  8912896ULL
#define W1_F   626688ULL
#define W2_F   1183744ULL
#define WL_F   (10ULL*W1_F + 2ULL*W2_F)

#define OFF_H    0ULL
#define OFF_GRE  (1ULL*MD_F)
#define OFF_GIM  (2ULL*MD_F)
#define OFF_Y    (3ULL*MD_F)
#define OFF_Z    (4ULL*MD_F)
#define OFF_H2   (5ULL*MD_F)
#define OFF_ACT  (7ULL*MD_F)
#define OFF_WB   (OFF_ACT + 10ULL*ACT_F)
#define OFF_POOL (OFF_WB + 3ULL*WL_F)
#define TOT_F    (OFF_POOL + 8192ULL)

__device__ __align__(1024) float g_scratch[TOT_F];

__device__ __forceinline__ float gelu_exact(float x) {
    return 0.5f * x * (1.0f + erff(x * 0.70710678118654752f));
}

__device__ __forceinline__ uint32_t smem_u32_of(const void* p) {
    uint32_t a;
    asm("{ .reg .u64 t; cvta.to.shared.u64 t, %1; cvt.u32.u64 %0, t; }"
        : "=r"(a) : "l"(p));
    return a;
}

__device__ __forceinline__ void split_bf16(float v, __nv_bfloat16& h, __nv_bfloat16& l) {
    h = __float2bfloat16(v);
    l = __float2bfloat16(v - __bfloat162float(h));
}

// ---------------------------------------------------------------------------
// mma.sync bf16x3 GEMM: C = alpha*(Ah+Al)(Bh+Bl)^T + beta*C
// 128x128 CTA tile, BK=64, 3-stage cp.async, 8 warps (64x32 each), 256 thr.
// One __syncthreads per K-chunk.
// ---------------------------------------------------------------------------
#define ROWB    144                   // 128B data + 16B pad (conflict-free)
#define PLANEB  (128*ROWB)            // 18432
#define STAGEB  (4*PLANEB)            // 73728
#define GEMM_SMEM_BYTES (3*STAGEB)    // 221184

#define CP_ASYNC_16(saddr, gptr) \
    asm volatile("cp.async.cg.shared.global [%0], [%1], 16;" \
        :: "r"(saddr), "l"(gptr) : "memory")
#define CP_COMMIT() asm volatile("cp.async.commit_group;" ::: "memory")
#define CP_WAIT_GROUP_1() asm volatile("cp.async.wait_group 1;" ::: "memory")

#define LDMATRIX_X4(r0, r1, r2, r3, addr) \
    asm volatile("ldmatrix.sync.aligned.m8n8.x4.shared.b16 {%0,%1,%2,%3}, [%4];" \
        : "=r"(r0), "=r"(r1), "=r"(r2), "=r"(r3) : "r"(addr))

#define MMA_BF16(c, a, b0, b1) \
    asm volatile("mma.sync.aligned.m16n8k16.row.col.f32.bf16.bf16.f32 " \
        "{%0,%1,%2,%3},{%4,%5,%6,%7},{%8,%9},{%0,%1,%2,%3};" \
        : "+f"((c)[0]), "+f"((c)[1]), "+f"((c)[2]), "+f"((c)[3]) \
        : "r"((a)[0]), "r"((a)[1]), "r"((a)[2]), "r"((a)[3]), "r"(b0), "r"(b1))

__global__ __launch_bounds__(256) void gemm_bf16x3(
    const __nv_bfloat16* __restrict__ Ah, const __nv_bfloat16* __restrict__ Al,
    const __nv_bfloat16* __restrict__ Bh, const __nv_bfloat16* __restrict__ Bl,
    float* __restrict__ C, int N, float alpha, float beta)
{
    extern __shared__ __align__(128) char smem[];
    const uint32_t sbase = smem_u32_of(smem);
    const int tid = threadIdx.x;
    const int wid = tid >> 5;
    const int lid = tid & 31;
    const int wm  = wid & 1;      // 2 warps in M
    const int wn  = wid >> 1;     // 4 warps in N

    const __nv_bfloat16* srcs[4];
    srcs[0] = Ah + (size_t)blockIdx.y * 128 * KP;
    srcs[1] = Al + (size_t)blockIdx.y * 128 * KP;
    srcs[2] = Bh + (size_t)blockIdx.x * 128 * KP;
    srcs[3] = Bl + (size_t)blockIdx.x * 128 * KP;

    // prefetch: 4 planes x 128 rows x 8 x 16B = 4096 chunks; 16 per thread
    auto prefetch = [&](int kc, int stage) {
        const int k0 = kc * 64;
        const uint32_t stb = sbase + stage * STAGEB;
        #pragma unroll
        for (int i = 0; i < 16; i++) {
            int c = i * 256 + tid;
            int pl = c >> 10;
            int r  = (c >> 3) & 127;
            int col = c & 7;
            CP_ASYNC_16(stb + pl * PLANEB + r * ROWB + col * 16,
                        srcs[pl] + (size_t)r * KP + k0 + col * 8);
        }
    };

    float acc[4][4][4];
    #pragma unroll
    for (int i = 0; i < 4; i++)
        #pragma unroll
        for (int j = 0; j < 4; j++)
            #pragma unroll
            for (int k = 0; k < 4; k++) acc[i][j][k] = 0.f;

    prefetch(0, 0); CP_COMMIT();
    prefetch(1, 1); CP_COMMIT();

    const int lrow = lid & 15;
    const int lcol = (lid >> 4) << 4;   // 0 or 16 bytes

    for (int kc = 0; kc < NCHUNK; kc++) {
        CP_WAIT_GROUP_1();     // group kc complete (kc+1 may be in flight)
        __syncthreads();       // all threads' stage-kc data visible; all
                               // warps past chunk kc-1 (stage (kc+2)%3 free)
        if (kc + 2 < NCHUNK) prefetch(kc + 2, (kc + 2) % 3);
        CP_COMMIT();           // empty group near tail keeps count correct

        const uint32_t stb = sbase + (kc % 3) * STAGEB;
        const uint32_t aHb = stb;
        const uint32_t aLb = stb + PLANEB;
        const uint32_t bHb = stb + 2 * PLANEB;
        const uint32_t bLb = stb + 3 * PLANEB;

        #pragma unroll
        for (int ks = 0; ks < 4; ks++) {
            uint32_t ah[4][4], al[4][4], bh[2][4], bl[2][4];
            #pragma unroll
            for (int mb = 0; mb < 4; mb++) {
                uint32_t off = (uint32_t)((wm * 64 + mb * 16 + lrow) * ROWB + ks * 32 + lcol);
                LDMATRIX_X4(ah[mb][0], ah[mb][1], ah[mb][2], ah[mb][3], aHb + off);
                LDMATRIX_X4(al[mb][0], al[mb][1], al[mb][2], al[mb][3], aLb + off);
            }
            #pragma unroll
            for (int p = 0; p < 2; p++) {
                uint32_t off = (uint32_t)((wn * 32 + p * 16 + lrow) * ROWB + ks * 32 + lcol);
                LDMATRIX_X4(bh[p][0], bh[p][1], bh[p][2], bh[p][3], bHb + off);
                LDMATRIX_X4(bl[p][0], bl[p][1], bl[p][2], bl[p][3], bLb + off);
            }
            // B x4 order: r0=n0-7/k0-7, r1=n8-15/k0-7, r2=n0-7/k8-15, r3=n8-15/k8-15
            // -> n-octet 0 uses (r0,r2), n-octet 1 uses (r1,r3).
            #pragma unroll
            for (int mb = 0; mb < 4; mb++) {
                #pragma unroll
                for (int nb = 0; nb < 4; nb++) {
                    uint32_t b0h = bh[nb >> 1][(nb & 1)];
                    uint32_t b1h = bh[nb >> 1][(nb & 1) + 2];
                    uint32_t b0l = bl[nb >> 1][(nb & 1)];
                    uint32_t b1l = bl[nb >> 1][(nb & 1) + 2];
                    MMA_BF16(acc[mb][nb], ah[mb], b0h, b1h);
                    MMA_BF16(acc[mb][nb], ah[mb], b0l, b1l);
                    MMA_BF16(acc[mb][nb], al[mb], b0h, b1h);
                }
            }
        }
    }

    // epilogue: registers -> gmem
    const int tig = lid & 3;
    const int grp = lid >> 2;
    const int mBase = blockIdx.y * 128 + wm * 64;
    const int nBase = blockIdx.x * 128 + wn * 32;
    #pragma unroll
    for (int mb = 0; mb < 4; mb++) {
        #pragma unroll
        for (int nb = 0; nb < 4; nb++) {
            int n = nBase + nb * 8 + tig * 2;
            if (n >= N) continue;
            int m0 = mBase + mb * 16 + grp;
            size_t i0 = (size_t)m0 * N + n;
            size_t i1 = (size_t)(m0 + 8) * N + n;
            float v0 = alpha * acc[mb][nb][0];
            float v1 = alpha * acc[mb][nb][1];
            float v2 = alpha * acc[mb][nb][2];
            float v3 = alpha * acc[mb][nb][3];
            if (beta != 0.f) {
                v0 = fmaf(beta, C[i0], v0);
                v1 = fmaf(beta, C[i0 + 1], v1);
                v2 = fmaf(beta, C[i1], v2);
                v3 = fmaf(beta, C[i1 + 1], v3);
            }
            *reinterpret_cast<float2*>(C + i0) = make_float2(v0, v1);
            *reinterpret_cast<float2*>(C + i1) = make_float2(v2, v3);
        }
    }
}

// ---------------------------------------------------------------------------
// Elementwise / row kernels
// ---------------------------------------------------------------------------
__global__ void enc_kernel(const float* __restrict__ x,
                           const float* __restrict__ ew,
                           const float* __restrict__ eb,
                           float* __restrict__ H)
{
    size_t i = (size_t)blockIdx.x * blockDim.x + threadIdx.x;
    if (i >= MD) return;
    int d = (int)(i % DM);
    int m = (int)(i / DM);
    H[i] = fmaf(x[m], ew[d], eb[d]);
}

__global__ __launch_bounds__(256) void ln2_kernel(
    const float* __restrict__ X,
    __nv_bfloat16* __restrict__ Oh, __nv_bfloat16* __restrict__ Ol,
    const float* __restrict__ w1, const float* __restrict__ b1,
    const float* __restrict__ w2, const float* __restrict__ b2)
{
    const int row = blockIdx.x;
    const int tid = threadIdx.x;
    const float* x = X + (size_t)row * DM;
    const size_t ro = (size_t)row * KP;
    __shared__ float sA[256], sB[256];

    float v[5];
    float s = 0.f, ss = 0.f;
    #pragma unroll
    for (int k = 0; k < 5; k++) {
        int d = tid + k * 256;
        float t = (d < DM) ? x[d] : 0.f;
        v[k] = t; s += t; ss += t * t;
    }
    sA[tid] = s; sB[tid] = ss; __syncthreads();
    for (int st = 128; st > 0; st >>= 1) {
        if (tid < st) { sA[tid] += sA[tid + st]; sB[tid] += sB[tid + st]; }
        __syncthreads();
    }
    float mu  = sA[0] * (1.0f / DM);
    float var = sB[0] * (1.0f / DM) - mu * mu;
    float rs  = rsqrtf(var + 1e-5f);
    __syncthreads();

    s = 0.f; ss = 0.f;
    #pragma unroll
    for (int k = 0; k < 5; k++) {
        int d = tid + k * 256;
        float r = 0.f;
        if (d < DM) r = fmaf((v[k] - mu) * rs, w1[d], b1[d]);
        v[k] = r; s += r; ss += r * r;
    }
    sA[tid] = s; sB[tid] = ss; __syncthreads();
    for (int st = 128; st > 0; st >>= 1) {
        if (tid < st) { sA[tid] += sA[tid + st]; sB[tid] += sB[tid + st]; }
        __syncthreads();
    }
    float mu2  = sA[0] * (1.0f / DM);
    float var2 = sB[0] * (1.0f / DM) - mu2 * mu2;
    float rs2  = rsqrtf(var2 + 1e-5f);
    #pragma unroll
    for (int k = 0; k < 5; k++) {
        int d = tid + k * 256;
        if (d < DM) {
            float r2 = fmaf((v[k] - mu2) * rs2, w2[d], b2[d]);
            __nv_bfloat16 h, l; split_bf16(r2, h, l);
            Oh[ro + d] = h; Ol[ro + d] = l;
        } else if (d < KP) {
            Oh[ro + d] = __float2bfloat16(0.f);
            Ol[ro + d] = __float2bfloat16(0.f);
        }
    }
}

__global__ __launch_bounds__(256) void postln_kernel(
    const float* __restrict__ Y,
    const __nv_bfloat16* __restrict__ FXh, const __nv_bfloat16* __restrict__ FXl,
    const float* __restrict__ dv,
    const float* __restrict__ w, const float* __restrict__ b,
    __nv_bfloat16* __restrict__ Oh, __nv_bfloat16* __restrict__ Ol)
{
    const int row = blockIdx.x;
    const int tid = threadIdx.x;
    const float* y = Y + (size_t)row * DM;
    const size_t ro = (size_t)row * KP;
    __shared__ float sA[256], sB[256];

    float v[5];
    float s = 0.f, ss = 0.f;
    #pragma unroll
    for (int k = 0; k < 5; k++) {
        int d = tid + k * 256;
        float z = 0.f;
        if (d < DM) {
            float f = __bfloat162float(FXh[ro + d]) + __bfloat162float(FXl[ro + d]);
            float e = fmaf(dv[d], f, y[d]);
            z = gelu_exact(e) + f;
        }
        v[k] = z; s += z; ss += z * z;
    }
    sA[tid] = s; sB[tid] = ss; __syncthreads();
    for (int st = 128; st > 0; st >>= 1) {
        if (tid < st) { sA[tid] += sA[tid + st]; sB[tid] += sB[tid + st]; }
        __syncthreads();
    }
    float mu  = sA[0] * (1.0f / DM);
    float var = sB[0] * (1.0f / DM) - mu * mu;
    float rs  = rsqrtf(var + 1e-5f);
    #pragma unroll
    for (int k = 0; k < 5; k++) {
        int d = tid + k * 256;
        if (d < DM) {
            float r = fmaf((v[k] - mu) * rs, w[d], b[d]);
            __nv_bfloat16 h, l; split_bf16(r, h, l);
            Oh[ro + d] = h; Ol[ro + d] = l;
        } else if (d < KP) {
            Oh[ro + d] = __float2bfloat16(0.f);
            Ol[ro + d] = __float2bfloat16(0.f);
        }
    }
}

__global__ void scan_kernel(
    const float* __restrict__ GRE, const float* __restrict__ GIM,
    __nv_bfloat16* __restrict__ XRh, __nv_bfloat16* __restrict__ XRl,
    __nv_bfloat16* __restrict__ XIh, __nv_bfloat16* __restrict__ XIl,
    const float* __restrict__ lr_, const float* __restrict__ li_,
    const float* __restrict__ ls_)
{
    int t = blockIdx.x * blockDim.x + threadIdx.x;
    if (t >= BSZ * PD) return;
    int b = t / PD, p = t % PD;

    float lr = lr_[p], li = li_[p];
    float st = expf(ls_[p]);
    float er = expf(lr * st);
    float sn, cs; sincosf(li * st, &sn, &cs);
    float ar = er * cs, ai = er * sn;
    float inv = 1.0f / (lr * lr + li * li);
    float nr = ar - 1.0f;
    float cr = (nr * lr + ai * li) * inv;
    float ci = (ai * lr - nr * li) * inv;

    size_t goff = (size_t)b * LSEQ * PD + p;
    const float* gr = GRE + goff;
    const float* gi = GIM + goff;
    size_t ooff = (size_t)b * LSEQ * KP + p;

    float xr = 0.f, xi = 0.f;
    #pragma unroll 4
    for (int l = 0; l < LSEQ; l++) {
        float ur = gr[(size_t)l * PD];
        float ui = gi[(size_t)l * PD];
        float br = fmaf(cr, ur, -ci * ui);
        float bi = fmaf(cr, ui,  ci * ur);
        float nxr = fmaf(ar, xr, fmaf(-ai, xi, br));
        float nxi = fmaf(ar, xi, fmaf( ai, xr, bi));
        xr = nxr; xi = nxi;
        size_t o = ooff + (size_t)l * KP;
        __nv_bfloat16 h, lo;
        split_bf16(xr, h, lo); XRh[o] = h; XRl[o] = lo;
        split_bf16(xi, h, lo); XIh[o] = h; XIl[o] = lo;
    }
}

__global__ void padscan_kernel(__nv_bfloat16* p0, __nv_bfloat16* p1,
                               __nv_bfloat16* p2, __nv_bfloat16* p3)
{
    int i = blockIdx.x * blockDim.x + threadIdx.x;
    const int PADW = KP - DM;
    if (i >= MROWS * PADW) return;
    int r = i / PADW, c = DM + i % PADW;
    size_t idx = (size_t)r * KP + c;
    __nv_bfloat16 z = __float2bfloat16(0.f);
    p0[idx] = z; p1[idx] = z; p2[idx] = z; p3[idx] = z;
}

__global__ void geglu_kernel(const float* __restrict__ H2,
                             __nv_bfloat16* __restrict__ Th,
                             __nv_bfloat16* __restrict__ Tl)
{
    size_t i = (size_t)blockIdx.x * blockDim.x + threadIdx.x;
    if (i >= (size_t)MROWS * KP) return;
    int d = (int)(i % KP);
    size_t m = i / KP;
    if (d < DM) {
        const float* r = H2 + m * (size_t)(2 * DM);
        float v = r[d] * gelu_exact(r[DM + d]);
        __nv_bfloat16 h, l; split_bf16(v, h, l);
        Th[i] = h; Tl[i] = l;
    } else {
        Th[i] = __float2bfloat16(0.f);
        Tl[i] = __float2bfloat16(0.f);
    }
}

__global__ void addres_kernel(float* __restrict__ H, const float* __restrict__ Z,
                              const __nv_bfloat16* __restrict__ FYh,
                              const __nv_bfloat16* __restrict__ FYl)
{
    size_t i = (size_t)blockIdx.x * blockDim.x + threadIdx.x;
    if (i >= MD) return;
    int d = (int)(i % DM);
    size_t m = i / DM;
    size_t j = m * KP + d;
    H[i] += Z[i] + __bfloat162float(FYh[j]) + __bfloat162float(FYl[j]);
}

// All 6 weights of one layer in ONE launch (blockIdx.y selects the weight)
__global__ void convw_layer_kernel(
    const float* __restrict__ Bre, const float* __restrict__ Bim,
    const float* __restrict__ Cre, const float* __restrict__ Cim,
    const float* __restrict__ Wd,  const float* __restrict__ We,
    __nv_bfloat16* __restrict__ L /* per-layer dst base */)
{
    const size_t W1E = (size_t)NP1 * KP;
    const size_t W2E = (size_t)NP2 * KP;
    int w = blockIdx.y;
    const float* src; __nv_bfloat16 *Wh, *Wl; int N; size_t tot;
    switch (w) {
        case 0: src = Bre; Wh = L;          Wl = L + 1*W1E; N = PD;   tot = W1E; break;
        case 1: src = Bim; Wh = L + 2*W1E;  Wl = L + 3*W1E; N = PD;   tot = W1E; break;
        case 2: src = Cre; Wh = L + 4*W1E;  Wl = L + 5*W1E; N = DM;   tot = W1E; break;
        case 3: src = Cim; Wh = L + 6*W1E;  Wl = L + 7*W1E; N = DM;   tot = W1E; break;
        case 4: src = Wd;  Wh = L + 8*W1E;  Wl = L + 9*W1E; N = DM;   tot = W1E; break;
        default:src = We;  Wh = L + 10*W1E; Wl = L + 10*W1E + W2E; N = 2*DM; tot = W2E; break;
    }
    size_t i = (size_t)blockIdx.x * blockDim.x + threadIdx.x;
    if (i >= tot) return;
    int n = (int)(i / KP), k = (int)(i % KP);
    float v = (n < N && k < DM) ? src[(size_t)n * DM + k] : 0.f;
    __nv_bfloat16 h, l; split_bf16(v, h, l);
    Wh[i] = h; Wl[i] = l;
}

__global__ void zero_kernel(float* __restrict__ P, int n)
{
    int i = blockIdx.x * blockDim.x + threadIdx.x;
    if (i < n) P[i] = 0.f;
}

#define POOL_CHUNKS 32
__global__ void pool_kernel(const float* __restrict__ H, float* __restrict__ POOL)
{
    int t = blockIdx.x * blockDim.x + threadIdx.x;
    if (t >= BSZ * DM) return;
    int b = t / DM, d = t % DM;
    const int CL = LSEQ / POOL_CHUNKS;
    int l0 = blockIdx.y * CL;
    const float* h = H + (size_t)b * LSEQ * DM + (size_t)l0 * DM + d;
    float s = 0.f;
    #pragma unroll 8
    for (int l = 0; l < CL; l++) s += h[(size_t)l * DM];
    atomicAdd(&POOL[t], s);
}

__global__ void head_kernel(const float* __restrict__ POOL,
                            const float* __restrict__ hw,
                            const float* __restrict__ hb,
                            float* __restrict__ out)
{
    int b = blockIdx.x;
    int tid = threadIdx.x;
    __shared__ float sA[256];
    float s = 0.f;
    for (int d = tid; d < DM; d += 256) s = fmaf(POOL[b * DM + d], hw[d], s);
    sA[tid] = s; __syncthreads();
    for (int st = 128; st > 0; st >>= 1) {
        if (tid < st) sA[tid] += sA[tid + st];
        __syncthreads();
    }
    if (tid == 0) out[b] = sA[0] * (1.0f / LSEQ) + hb[0];
}

// ---------------------------------------------------------------------------
// kernel_launch
// ---------------------------------------------------------------------------
extern "C" void kernel_launch(void* const* d_in, const int* in_sizes, int n_in,
                              void* d_out, int out_size)
{
    const float* x           = (const float*)d_in[0];
    const float* enc_w       = (const float*)d_in[1];
    const float* enc_b       = (const float*)d_in[2];
    const float* norm_w      = (const float*)d_in[3];
    const float* norm_b      = (const float*)d_in[4];
    const float* attn_norm_w = (const float*)d_in[5];
    const float* attn_norm_b = (const float*)d_in[6];
    const float* ff_norm_w   = (const float*)d_in[7];
    const float* ff_norm_b   = (const float*)d_in[8];
    const float* lam_re      = (const float*)d_in[9];
    const float* lam_im      = (const float*)d_in[10];
    const float* log_step    = (const float*)d_in[11];
    const float* B_re        = (const float*)d_in[12];
    const float* B_im        = (const float*)d_in[13];
    const float* C_re        = (const float*)d_in[14];
    const float* C_im        = (const float*)d_in[15];
    const float* Dvec        = (const float*)d_in[16];
    const float* Wenc        = (const float*)d_in[17];
    const float* Wdec        = (const float*)d_in[18];
    const float* head_w      = (const float*)d_in[19];
    const float* head_b      = (const float*)d_in[20];
    float* out = (float*)d_out;

    float* base = nullptr;
    cudaGetSymbolAddress((void**)&base, g_scratch);

    float* H    = base + OFF_H;
    float* GRE  = base + OFF_GRE;
    float* GIM  = base + OFF_GIM;
    float* Y    = base + OFF_Y;
    float* Z    = base + OFF_Z;
    float* H2   = base + OFF_H2;
    float* POOL = base + OFF_POOL;

    __nv_bfloat16* actb = (__nv_bfloat16*)(base + OFF_ACT);
    const size_t AE = (size_t)MROWS * KP;
    __nv_bfloat16* FXh = actb + 0 * AE;
    __nv_bfloat16* FXl = actb + 1 * AE;
    __nv_bfloat16* XRh = actb + 2 * AE;
    __nv_bfloat16* XRl = actb + 3 * AE;
    __nv_bfloat16* XIh = actb + 4 * AE;
    __nv_bfloat16* XIl = actb + 5 * AE;
    __nv_bfloat16* FYh = actb + 6 * AE;
    __nv_bfloat16* FYl = actb + 7 * AE;
    __nv_bfloat16* Th  = actb + 8 * AE;
    __nv_bfloat16* Tl  = actb + 9 * AE;

    __nv_bfloat16* wb = (__nv_bfloat16*)(base + OFF_WB);
    const size_t W1E = (size_t)NP1 * KP;
    const size_t W2E = (size_t)NP2 * KP;
    const size_t WLE = 10 * W1E + 2 * W2E;

    cudaFuncSetAttribute(gemm_bf16x3, cudaFuncAttributeMaxDynamicSharedMemorySize,
                         GEMM_SMEM_BYTES);

    const int EW_BLOCKS = (int)((MD + 255) / 256);

    // Launch order puts the FIRST GEMM at launch #6 so ncu (-s 5 -c 1)
    // finally profiles the GEMM: enc, convw x3, ln2, gemm, ...
    enc_kernel<<<EW_BLOCKS, 256>>>(x, enc_w, enc_b, H);   // 1

    {
        dim3 gw((unsigned)((W2E + 255) / 256), 6);
        for (int i = 0; i < NLAYERS; i++) {               // 2,3,4
            convw_layer_kernel<<<gw, 256>>>(
                B_re + (size_t)i*PD*DM, B_im + (size_t)i*PD*DM,
                C_re + (size_t)i*DM*PD, C_im + (size_t)i*DM*PD,
                Wdec + (size_t)i*DM*DM, Wenc + (size_t)i*2*DM*DM,
                wb + (size_t)i * WLE);
        }
    }

    dim3 g9(NP1 / 128, MROWS / 128);
    dim3 g17(NP2 / 128, MROWS / 128);
    bool padded = false;

    for (int i = 0; i < NLAYERS; i++) {
        const float* nw  = norm_w      + (size_t)i * DM;
        const float* nb  = norm_b      + (size_t)i * DM;
        const float* aw  = attn_norm_w + (size_t)i * DM;
        const float* ab  = attn_norm_b + (size_t)i * DM;
        const float* fw  = ff_norm_w   + (size_t)i * DM;
        const float* fb  = ff_norm_b   + (size_t)i * DM;
        const float* lre = lam_re      + (size_t)i * PD;
        const float* lim = lam_im      + (size_t)i * PD;
        const float* lst = log_step    + (size_t)i * PD;
        const float* dv  = Dvec        + (size_t)i * DM;

        __nv_bfloat16* L = wb + (size_t)i * WLE;
        __nv_bfloat16* Breh = L;             __nv_bfloat16* Brel = L + 1*W1E;
        __nv_bfloat16* Bimh = L + 2*W1E;     __nv_bfloat16* Biml = L + 3*W1E;
        __nv_bfloat16* Creh = L + 4*W1E;     __nv_bfloat16* Crel = L + 5*W1E;
        __nv_bfloat16* Cimh = L + 6*W1E;     __nv_bfloat16* Ciml = L + 7*W1E;
        __nv_bfloat16* Wdh  = L + 8*W1E;     __nv_bfloat16* Wdl  = L + 9*W1E;
        __nv_bfloat16* Weh  = L + 10*W1E;    __nv_bfloat16* Wel  = L + 10*W1E + W2E;

        ln2_kernel<<<MROWS, 256>>>(H, FXh, FXl, nw, nb, aw, ab);   // 5 (i=0)

        gemm_bf16x3<<<g9, 256, GEMM_SMEM_BYTES>>>(FXh, FXl, Breh, Brel, GRE, PD, 1.f, 0.f); // 6!
        gemm_bf16x3<<<g9, 256, GEMM_SMEM_BYTES>>>(FXh, FXl, Bimh, Biml, GIM, PD, 1.f, 0.f);

        if (!padded) {
            int npad = MROWS * (KP - DM);
            padscan_kernel<<<(npad + 255) / 256, 256>>>(XRh, XRl, XIh, XIl);
            padded = true;
        }

        scan_kernel<<<(BSZ * PD + 127) / 128, 128>>>(GRE, GIM, XRh, XRl, XIh, XIl,
                                                     lre, lim, lst);

        gemm_bf16x3<<<g9, 256, GEMM_SMEM_BYTES>>>(XRh, XRl, Creh, Crel, Y, DM, 1.f, 0.f);
        gemm_bf16x3<<<g9, 256, GEMM_SMEM_BYTES>>>(XIh, XIl, Cimh, Ciml, Y, DM, -1.f, 1.f);

        postln_kernel<<<MROWS, 256>>>(Y, FXh, FXl, dv, fw, fb, FYh, FYl);

        gemm_bf16x3<<<g17, 256, GEMM_SMEM_BYTES>>>(FYh, FYl, Weh, Wel, H2, 2 * DM, 1.f, 0.f);

        {
            size_t n = (size_t)MROWS * KP;
            geglu_kernel<<<(int)((n + 255) / 256), 256>>>(H2, Th, Tl);
        }

        gemm_bf16x3<<<g9, 256, GEMM_SMEM_BYTES>>>(Th, Tl, Wdh, Wdl, Z, DM, 1.f, 0.f);

        addres_kernel<<<EW_BLOCKS, 256>>>(H, Z, FYh, FYl);
    }

    zero_kernel<<<(BSZ * DM + 255) / 256, 256>>>(POOL, BSZ * DM);
    dim3 gp((BSZ * DM + 127) / 128, POOL_CHUNKS);
    pool_kernel<<<gp, 128>>>(H, POOL);
    head_kernel<<<BSZ, 256>>>(POOL, head_w, head_b, out);
}

// round 7
// speedup vs baseline: 2.1774x; 1.2274x over previous
#include <cuda_runtime.h>
#include <cuda_bf16.h>
#include <math.h>
#include <cstdint>

// ---------------------------------------------------------------------------
// Problem constants
// ---------------------------------------------------------------------------
#define BSZ     4
#define LSEQ    4096
#define DM      1048
#define PD      1048
#define NLAYERS 3
#define MROWS   (BSZ*LSEQ)              // 16384
#define MD      ((size_t)MROWS * DM)
#define KP      1088                    // K padded to multiple of 64
#define NCHUNK  (KP/64)                 // 17
#define NP1     1152
#define NP2     2176

#define MD_F   17170432ULL
#define ACT_F  8912896ULL
#define W1_F   626688ULL
#define W2_F   1183744ULL
#define WL_F   (10ULL*W1_F + 2ULL*W2_F)

#define OFF_H    0ULL
#define OFF_GRE  (1ULL*MD_F)
#define OFF_GIM  (2ULL*MD_F)
#define OFF_Y    (3ULL*MD_F)
#define OFF_Z    (4ULL*MD_F)
#define OFF_H2   (5ULL*MD_F)
#define OFF_ACT  (7ULL*MD_F)
#define OFF_WB   (OFF_ACT + 10ULL*ACT_F)
#define OFF_POOL (OFF_WB + 3ULL*WL_F)
#define TOT_F    (OFF_POOL + 8192ULL)

__device__ __align__(1024) float g_scratch[TOT_F];

// tcgen05 only exists in the sm_103a-specific pass; generic pass gets the
// (slower but correct) mma.sync body below.
#if defined(__CUDA_ARCH_FEAT_SM103_ALL) || defined(__CUDA_ARCH_SPECIFIC__) || defined(__CUDA_ARCH_FEAT_SM100_ALL)
#define HAS_TCGEN05 1
#else
#define HAS_TCGEN05 0
#endif

__device__ __forceinline__ float gelu_exact(float x) {
    return 0.5f * x * (1.0f + erff(x * 0.70710678118654752f));
}

__device__ __forceinline__ uint32_t smem_u32_of(const void* p) {
    uint32_t a;
    asm("{ .reg .u64 t; cvta.to.shared.u64 t, %1; cvt.u32.u64 %0, t; }"
        : "=r"(a) : "l"(p));
    return a;
}

__device__ __forceinline__ void split_bf16(float v, __nv_bfloat16& h, __nv_bfloat16& l) {
    h = __float2bfloat16(v);
    l = __float2bfloat16(v - __bfloat162float(h));
}

__device__ __forceinline__ uint32_t elect_one_pred() {
    uint32_t pred;
    asm volatile(
        "{\n\t.reg .pred p;\n\telect.sync _|p, 0xFFFFFFFF;\n\t"
        "selp.b32 %0, 1, 0, p;\n\t}" : "=r"(pred));
    return pred;
}

// ---------------------------------------------------------------------------
// Shared PTX macros
// ---------------------------------------------------------------------------
#define CP_ASYNC_16(saddr, gptr) \
    asm volatile("cp.async.cg.shared.global [%0], [%1], 16;" \
        :: "r"(saddr), "l"(gptr) : "memory")
#define CP_COMMIT() asm volatile("cp.async.commit_group;" ::: "memory")
#define CP_WAIT_GROUP_1() asm volatile("cp.async.wait_group 1;" ::: "memory")

#define LDMATRIX_X4(r0, r1, r2, r3, addr) \
    asm volatile("ldmatrix.sync.aligned.m8n8.x4.shared.b16 {%0,%1,%2,%3}, [%4];" \
        : "=r"(r0), "=r"(r1), "=r"(r2), "=r"(r3) : "r"(addr))

#define MMA_BF16(c, a, b0, b1) \
    asm volatile("mma.sync.aligned.m16n8k16.row.col.f32.bf16.bf16.f32 " \
        "{%0,%1,%2,%3},{%4,%5,%6,%7},{%8,%9},{%0,%1,%2,%3};" \
        : "+f"((c)[0]), "+f"((c)[1]), "+f"((c)[2]), "+f"((c)[3]) \
        : "r"((a)[0]), "r"((a)[1]), "r"((a)[2]), "r"((a)[3]), "r"(b0), "r"(b1))

#define MBARRIER_INIT(mbar, count) \
    asm volatile("mbarrier.init.shared.b64 [%0], %1;" \
        :: "r"((uint32_t)(mbar)), "r"((uint32_t)(count)) : "memory")
#define MBARRIER_WAIT_PARITY(mbar, parity) do { \
    uint32_t _mbar = (uint32_t)(mbar); \
    uint32_t _parity = (uint32_t)(parity); \
    uint32_t _done; \
    asm volatile( \
        "{\n\t.reg .pred p;\n\t" \
        "mbarrier.try_wait.parity.acquire.cta.shared::cta.b64 p, [%1], %2;\n\t" \
        "selp.b32 %0, 1, 0, p;\n\t}" \
        : "=r"(_done) : "r"(_mbar), "r"(_parity) : "memory"); \
    if (!_done) { \
        asm volatile( \
            "{\n\t.reg .pred P1;\n\t" \
            "WAIT_LOOP_%=:\n\t" \
            "mbarrier.try_wait.parity.acquire.cta.shared::cta.b64 P1, [%0], %1, 0x989680;\n\t" \
            "@P1 bra.uni WAIT_DONE_%=;\n\t" \
            "bra.uni WAIT_LOOP_%=;\n\t" \
            "WAIT_DONE_%=:\n\t}" \
            :: "r"(_mbar), "r"(_parity) : "memory"); \
    } \
} while(0)

#define GEMM_SMEM_BYTES 221184

#if HAS_TCGEN05
// ===== tcgen05 path ==========================================================
#define TCGEN05_ALLOC(saddr, nCols) \
    asm volatile("tcgen05.alloc.cta_group::1.sync.aligned.shared::cta.b32 [%0], %1;" \
        :: "r"((uint32_t)(saddr)), "r"((uint32_t)(nCols)) : "memory")
#define TCGEN05_DEALLOC(tmem, nCols) \
    asm volatile("tcgen05.dealloc.cta_group::1.sync.aligned.b32 %0, %1;" \
        :: "r"(tmem), "r"((uint32_t)(nCols)))
#define TCGEN05_RELINQUISH() \
    asm volatile("tcgen05.relinquish_alloc_permit.cta_group::1.sync.aligned;")
#define TCGEN05_COMMIT(mbar) \
    asm volatile("tcgen05.commit.cta_group::1.mbarrier::arrive::one.shared::cluster.b64 [%0];" \
        :: "r"((uint32_t)(mbar)) : "memory")
#define TCGEN05_FENCE_AFTER() \
    asm volatile("tcgen05.fence::after_thread_sync;" ::: "memory")
#define TCGEN05_WAIT_LD() \
    asm volatile("tcgen05.wait::ld.sync.aligned;" ::: "memory")
#define FENCE_PROXY_ASYNC() \
    asm volatile("fence.proxy.async.shared::cta;" ::: "memory")
#define TCGEN05_LD_32X32B_X32(r, taddr) \
    asm volatile( \
        "tcgen05.ld.sync.aligned.32x32b.x32.b32 " \
        "{%0, %1, %2, %3, %4, %5, %6, %7, " \
        " %8, %9, %10, %11, %12, %13, %14, %15, " \
        " %16, %17, %18, %19, %20, %21, %22, %23, " \
        " %24, %25, %26, %27, %28, %29, %30, %31}, [%32];" \
        : "=r"((r)[0]),  "=r"((r)[1]),  "=r"((r)[2]),  "=r"((r)[3]), \
          "=r"((r)[4]),  "=r"((r)[5]),  "=r"((r)[6]),  "=r"((r)[7]), \
          "=r"((r)[8]),  "=r"((r)[9]),  "=r"((r)[10]), "=r"((r)[11]), \
          "=r"((r)[12]), "=r"((r)[13]), "=r"((r)[14]), "=r"((r)[15]), \
          "=r"((r)[16]), "=r"((r)[17]), "=r"((r)[18]), "=r"((r)[19]), \
          "=r"((r)[20]), "=r"((r)[21]), "=r"((r)[22]), "=r"((r)[23]), \
          "=r"((r)[24]), "=r"((r)[25]), "=r"((r)[26]), "=r"((r)[27]), \
          "=r"((r)[28]), "=r"((r)[29]), "=r"((r)[30]), "=r"((r)[31]) \
        : "r"(taddr))

static constexpr uint64_t SMEM_DESC_BASE_SW128 =
    (uint64_t(2) << 61) | (uint64_t(1) << 46) | (uint64_t(64) << 32) | (uint64_t(1) << 16);
#define MAKE_SMEM_DESC(base_addr) \
    (SMEM_DESC_BASE_SW128 | ((uint64_t)((base_addr) >> 4) & 0x3FFF))

// idesc: kind::f16, dtype=F32, atype=btype=BF16, M=128, N=128
static constexpr uint32_t GIDESC =
    (1u<<4) | (1u<<7) | (1u<<10) | ((128u/8u)<<17) | ((128u/16u)<<24);

__device__ __forceinline__ void mma_f16_ss(uint32_t d_tmem, uint64_t a_desc,
                                           uint64_t b_desc, uint32_t en) {
    asm volatile(
        "{\n\t.reg .pred p;\n\tsetp.ne.u32 p, %4, 0;\n\t"
        "tcgen05.mma.cta_group::1.kind::f16 [%0], %1, %2, %3, {%5, %5, %5, %5}, p;\n\t}"
        :: "r"(d_tmem), "l"(a_desc), "l"(b_desc), "r"(GIDESC), "r"(en), "r"(0u)
        : "memory");
}

#define TPLANE 16384
#define TSTAGE 65536

__global__ __launch_bounds__(256) void gemm_bf16x3(
    const __nv_bfloat16* __restrict__ Ah, const __nv_bfloat16* __restrict__ Al,
    const __nv_bfloat16* __restrict__ Bh, const __nv_bfloat16* __restrict__ Bl,
    float* __restrict__ C, int N, float alpha, float beta)
{
    extern __shared__ __align__(1024) char smem[];
    const uint32_t sbase = smem_u32_of(smem);
    const int tid = threadIdx.x;
    const int wid = tid >> 5;
    const int lid = tid & 31;

    if (wid == 0) {
        TCGEN05_ALLOC(sbase + 0, 128);
        TCGEN05_RELINQUISH();
    }
    if (tid == 0) {
        MBARRIER_INIT(sbase + 16, 1);
        MBARRIER_INIT(sbase + 24, 1);
        MBARRIER_INIT(sbase + 32, 1);
    }
    __syncthreads();
    uint32_t tmem;
    asm volatile("ld.shared.b32 %0, [%1];" : "=r"(tmem) : "r"(sbase));

    const __nv_bfloat16* srcs[4];
    srcs[0] = Ah + (size_t)blockIdx.y * 128 * KP;
    srcs[1] = Al + (size_t)blockIdx.y * 128 * KP;
    srcs[2] = Bh + (size_t)blockIdx.x * 128 * KP;
    srcs[3] = Bl + (size_t)blockIdx.x * 128 * KP;

    // 4 planes x 128 rows x 8 x 16B = 4096 chunks, 16 per thread.
    // SW128 swizzle at 16B granularity: unit j -> j ^ (row & 7).
    auto prefetch = [&](int kc, int stage) {
        const int k0 = kc * 64;
        const uint32_t stb = sbase + 1024 + stage * TSTAGE;
        #pragma unroll
        for (int i = 0; i < 16; i++) {
            int c  = i * 256 + tid;
            int pl = c >> 10;
            int r  = (c >> 3) & 127;
            int j  = c & 7;
            uint32_t dst = stb + pl * TPLANE + r * 128 + ((j ^ (r & 7)) << 4);
            CP_ASYNC_16(dst, srcs[pl] + (size_t)r * KP + k0 + j * 8);
        }
    };

    prefetch(0, 0); CP_COMMIT();
    prefetch(1, 1); CP_COMMIT();

    for (int kc = 0; kc < NCHUNK; kc++) {
        CP_WAIT_GROUP_1();            // stage kc's cp.async group complete
        __syncthreads();
        FENCE_PROXY_ASYNC();          // generic->async proxy visibility

        if (wid == 0 && elect_one_pred()) {
            const uint32_t stb = sbase + 1024 + (kc % 3) * TSTAGE;
            uint64_t dAh = MAKE_SMEM_DESC(stb);
            uint64_t dAl = MAKE_SMEM_DESC(stb + TPLANE);
            uint64_t dBh = MAKE_SMEM_DESC(stb + 2 * TPLANE);
            uint64_t dBl = MAKE_SMEM_DESC(stb + 3 * TPLANE);
            #pragma unroll
            for (int ks = 0; ks < 4; ks++) {
                mma_f16_ss(tmem, dAh + ks * 2, dBh + ks * 2, (kc != 0) || (ks != 0));
                mma_f16_ss(tmem, dAh + ks * 2, dBl + ks * 2, 1u);
                mma_f16_ss(tmem, dAl + ks * 2, dBh + ks * 2, 1u);
            }
            TCGEN05_COMMIT(sbase + 16 + 8 * (kc % 3));
        }

        // Before refilling stage (kc+2)%3 == (kc-1)%3 we must know chunk
        // kc-1's MMAs finished reading it.
        if (kc >= 1) {
            int pc = kc - 1;
            MBARRIER_WAIT_PARITY(sbase + 16 + 8 * (pc % 3), (pc / 3) & 1);
        }
        if (kc + 2 < NCHUNK) prefetch(kc + 2, (kc + 2) % 3);
        CP_COMMIT();
    }
    {
        int pc = NCHUNK - 1;
        MBARRIER_WAIT_PARITY(sbase + 16 + 8 * (pc % 3), (pc / 3) & 1);
    }
    TCGEN05_FENCE_AFTER();

    // epilogue: warps 0-3 read TMEM (lane = M row within tile)
    if (wid < 4) {
        const int nbase = blockIdx.x * 128;
        const size_t m = (size_t)blockIdx.y * 128 + wid * 32 + lid;
        float* crow = C + m * (size_t)N;
        for (int cb = 0; cb < 4; cb++) {
            uint32_t r[32];
            TCGEN05_LD_32X32B_X32(r, tmem + cb * 32);
            TCGEN05_WAIT_LD();
            #pragma unroll
            for (int c = 0; c < 32; c++) {
                int n = nbase + cb * 32 + c;
                if (n < N) {
                    float v = alpha * __uint_as_float(r[c]);
                    if (beta != 0.f) v = fmaf(beta, crow[n], v);
                    crow[n] = v;
                }
            }
        }
    }
    __syncthreads();
    if (wid == 0) TCGEN05_DEALLOC(tmem, 128);
}

#else
// ===== mma.sync fallback (the R6 kernel — correct, ~630us/GEMM) =============
#define ROWB    144
#define PLANEB  (128*ROWB)
#define STAGEB  (4*PLANEB)

__global__ __launch_bounds__(256) void gemm_bf16x3(
    const __nv_bfloat16* __restrict__ Ah, const __nv_bfloat16* __restrict__ Al,
    const __nv_bfloat16* __restrict__ Bh, const __nv_bfloat16* __restrict__ Bl,
    float* __restrict__ C, int N, float alpha, float beta)
{
    extern __shared__ __align__(128) char smem[];
    const uint32_t sbase = smem_u32_of(smem);
    const int tid = threadIdx.x;
    const int wid = tid >> 5;
    const int lid = tid & 31;
    const int wm  = wid & 1;
    const int wn  = wid >> 1;

    const __nv_bfloat16* srcs[4];
    srcs[0] = Ah + (size_t)blockIdx.y * 128 * KP;
    srcs[1] = Al + (size_t)blockIdx.y * 128 * KP;
    srcs[2] = Bh + (size_t)blockIdx.x * 128 * KP;
    srcs[3] = Bl + (size_t)blockIdx.x * 128 * KP;

    auto prefetch = [&](int kc, int stage) {
        const int k0 = kc * 64;
        const uint32_t stb = sbase + stage * STAGEB;
        #pragma unroll
        for (int i = 0; i < 16; i++) {
            int c = i * 256 + tid;
            int pl = c >> 10;
            int r  = (c >> 3) & 127;
            int col = c & 7;
            CP_ASYNC_16(stb + pl * PLANEB + r * ROWB + col * 16,
                        srcs[pl] + (size_t)r * KP + k0 + col * 8);
        }
    };

    float acc[4][4][4];
    #pragma unroll
    for (int i = 0; i < 4; i++)
        #pragma unroll
        for (int j = 0; j < 4; j++)
            #pragma unroll
            for (int k = 0; k < 4; k++) acc[i][j][k] = 0.f;

    prefetch(0, 0); CP_COMMIT();
    prefetch(1, 1); CP_COMMIT();

    const int lrow = lid & 15;
    const int lcol = (lid >> 4) << 4;

    for (int kc = 0; kc < NCHUNK; kc++) {
        CP_WAIT_GROUP_1();
        __syncthreads();
        if (kc + 2 < NCHUNK) prefetch(kc + 2, (kc + 2) % 3);
        CP_COMMIT();

        const uint32_t stb = sbase + (kc % 3) * STAGEB;
        const uint32_t aHb = stb;
        const uint32_t aLb = stb + PLANEB;
        const uint32_t bHb = stb + 2 * PLANEB;
        const uint32_t bLb = stb + 3 * PLANEB;

        #pragma unroll
        for (int ks = 0; ks < 4; ks++) {
            uint32_t ah[4][4], al[4][4], bh[2][4], bl[2][4];
            #pragma unroll
            for (int mb = 0; mb < 4; mb++) {
                uint32_t off = (uint32_t)((wm * 64 + mb * 16 + lrow) * ROWB + ks * 32 + lcol);
                LDMATRIX_X4(ah[mb][0], ah[mb][1], ah[mb][2], ah[mb][3], aHb + off);
                LDMATRIX_X4(al[mb][0], al[mb][1], al[mb][2], al[mb][3], aLb + off);
            }
            #pragma unroll
            for (int p = 0; p < 2; p++) {
                uint32_t off = (uint32_t)((wn * 32 + p * 16 + lrow) * ROWB + ks * 32 + lcol);
                LDMATRIX_X4(bh[p][0], bh[p][1], bh[p][2], bh[p][3], bHb + off);
                LDMATRIX_X4(bl[p][0], bl[p][1], bl[p][2], bl[p][3], bLb + off);
            }
            #pragma unroll
            for (int mb = 0; mb < 4; mb++) {
                #pragma unroll
                for (int nb = 0; nb < 4; nb++) {
                    uint32_t b0h = bh[nb >> 1][(nb & 1)];
                    uint32_t b1h = bh[nb >> 1][(nb & 1) + 2];
                    uint32_t b0l = bl[nb >> 1][(nb & 1)];
                    uint32_t b1l = bl[nb >> 1][(nb & 1) + 2];
                    MMA_BF16(acc[mb][nb], ah[mb], b0h, b1h);
                    MMA_BF16(acc[mb][nb], ah[mb], b0l, b1l);
                    MMA_BF16(acc[mb][nb], al[mb], b0h, b1h);
                }
            }
        }
    }

    const int tig = lid & 3;
    const int grp = lid >> 2;
    const int mBase = blockIdx.y * 128 + wm * 64;
    const int nBase = blockIdx.x * 128 + wn * 32;
    #pragma unroll
    for (int mb = 0; mb < 4; mb++) {
        #pragma unroll
        for (int nb = 0; nb < 4; nb++) {
            int n = nBase + nb * 8 + tig * 2;
            if (n >= N) continue;
            int m0 = mBase + mb * 16 + grp;
            size_t i0 = (size_t)m0 * N + n;
            size_t i1 = (size_t)(m0 + 8) * N + n;
            float v0 = alpha * acc[mb][nb][0];
            float v1 = alpha * acc[mb][nb][1];
            float v2 = alpha * acc[mb][nb][2];
            float v3 = alpha * acc[mb][nb][3];
            if (beta != 0.f) {
                v0 = fmaf(beta, C[i0], v0);
                v1 = fmaf(beta, C[i0 + 1], v1);
                v2 = fmaf(beta, C[i1], v2);
                v3 = fmaf(beta, C[i1 + 1], v3);
            }
            *reinterpret_cast<float2*>(C + i0) = make_float2(v0, v1);
            *reinterpret_cast<float2*>(C + i1) = make_float2(v2, v3);
        }
    }
}
#endif

// ---------------------------------------------------------------------------
// Elementwise / row kernels (unchanged from R6)
// ---------------------------------------------------------------------------
__global__ void enc_kernel(const float* __restrict__ x,
                           const float* __restrict__ ew,
                           const float* __restrict__ eb,
                           float* __restrict__ H)
{
    size_t i = (size_t)blockIdx.x * blockDim.x + threadIdx.x;
    if (i >= MD) return;
    int d = (int)(i % DM);
    int m = (int)(i / DM);
    H[i] = fmaf(x[m], ew[d], eb[d]);
}

__global__ __launch_bounds__(256) void ln2_kernel(
    const float* __restrict__ X,
    __nv_bfloat16* __restrict__ Oh, __nv_bfloat16* __restrict__ Ol,
    const float* __restrict__ w1, const float* __restrict__ b1,
    const float* __restrict__ w2, const float* __restrict__ b2)
{
    const int row = blockIdx.x;
    const int tid = threadIdx.x;
    const float* x = X + (size_t)row * DM;
    const size_t ro = (size_t)row * KP;
    __shared__ float sA[256], sB[256];

    float v[5];
    float s = 0.f, ss = 0.f;
    #pragma unroll
    for (int k = 0; k < 5; k++) {
        int d = tid + k * 256;
        float t = (d < DM) ? x[d] : 0.f;
        v[k] = t; s += t; ss += t * t;
    }
    sA[tid] = s; sB[tid] = ss; __syncthreads();
    for (int st = 128; st > 0; st >>= 1) {
        if (tid < st) { sA[tid] += sA[tid + st]; sB[tid] += sB[tid + st]; }
        __syncthreads();
    }
    float mu  = sA[0] * (1.0f / DM);
    float var = sB[0] * (1.0f / DM) - mu * mu;
    float rs  = rsqrtf(var + 1e-5f);
    __syncthreads();

    s = 0.f; ss = 0.f;
    #pragma unroll
    for (int k = 0; k < 5; k++) {
        int d = tid + k * 256;
        float r = 0.f;
        if (d < DM) r = fmaf((v[k] - mu) * rs, w1[d], b1[d]);
        v[k] = r; s += r; ss += r * r;
    }
    sA[tid] = s; sB[tid] = ss; __syncthreads();
    for (int st = 128; st > 0; st >>= 1) {
        if (tid < st) { sA[tid] += sA[tid + st]; sB[tid] += sB[tid + st]; }
        __syncthreads();
    }
    float mu2  = sA[0] * (1.0f / DM);
    float var2 = sB[0] * (1.0f / DM) - mu2 * mu2;
    float rs2  = rsqrtf(var2 + 1e-5f);
    #pragma unroll
    for (int k = 0; k < 5; k++) {
        int d = tid + k * 256;
        if (d < DM) {
            float r2 = fmaf((v[k] - mu2) * rs2, w2[d], b2[d]);
            __nv_bfloat16 h, l; split_bf16(r2, h, l);
            Oh[ro + d] = h; Ol[ro + d] = l;
        } else if (d < KP) {
            Oh[ro + d] = __float2bfloat16(0.f);
            Ol[ro + d] = __float2bfloat16(0.f);
        }
    }
}

__global__ __launch_bounds__(256) void postln_kernel(
    const float* __restrict__ Y,
    const __nv_bfloat16* __restrict__ FXh, const __nv_bfloat16* __restrict__ FXl,
    const float* __restrict__ dv,
    const float* __restrict__ w, const float* __restrict__ b,
    __nv_bfloat16* __restrict__ Oh, __nv_bfloat16* __restrict__ Ol)
{
    const int row = blockIdx.x;
    const int tid = threadIdx.x;
    const float* y = Y + (size_t)row * DM;
    const size_t ro = (size_t)row * KP;
    __shared__ float sA[256], sB[256];

    float v[5];
    float s = 0.f, ss = 0.f;
    #pragma unroll
    for (int k = 0; k < 5; k++) {
        int d = tid + k * 256;
        float z = 0.f;
        if (d < DM) {
            float f = __bfloat162float(FXh[ro + d]) + __bfloat162float(FXl[ro + d]);
            float e = fmaf(dv[d], f, y[d]);
            z = gelu_exact(e) + f;
        }
        v[k] = z; s += z; ss += z * z;
    }
    sA[tid] = s; sB[tid] = ss; __syncthreads();
    for (int st = 128; st > 0; st >>= 1) {
        if (tid < st) { sA[tid] += sA[tid + st]; sB[tid] += sB[tid + st]; }
        __syncthreads();
    }
    float mu  = sA[0] * (1.0f / DM);
    float var = sB[0] * (1.0f / DM) - mu * mu;
    float rs  = rsqrtf(var + 1e-5f);
    #pragma unroll
    for (int k = 0; k < 5; k++) {
        int d = tid + k * 256;
        if (d < DM) {
            float r = fmaf((v[k] - mu) * rs, w[d], b[d]);
            __nv_bfloat16 h, l; split_bf16(r, h, l);
            Oh[ro + d] = h; Ol[ro + d] = l;
        } else if (d < KP) {
            Oh[ro + d] = __float2bfloat16(0.f);
            Ol[ro + d] = __float2bfloat16(0.f);
        }
    }
}

__global__ void scan_kernel(
    const float* __restrict__ GRE, const float* __restrict__ GIM,
    __nv_bfloat16* __restrict__ XRh, __nv_bfloat16* __restrict__ XRl,
    __nv_bfloat16* __restrict__ XIh, __nv_bfloat16* __restrict__ XIl,
    const float* __restrict__ lr_, const float* __restrict__ li_,
    const float* __restrict__ ls_)
{
    int t = blockIdx.x * blockDim.x + threadIdx.x;
    if (t >= BSZ * PD) return;
    int b = t / PD, p = t % PD;

    float lr = lr_[p], li = li_[p];
    float st = expf(ls_[p]);
    float er = expf(lr * st);
    float sn, cs; sincosf(li * st, &sn, &cs);
    float ar = er * cs, ai = er * sn;
    float inv = 1.0f / (lr * lr + li * li);
    float nr = ar - 1.0f;
    float cr = (nr * lr + ai * li) * inv;
    float ci = (ai * lr - nr * li) * inv;

    size_t goff = (size_t)b * LSEQ * PD + p;
    const float* gr = GRE + goff;
    const float* gi = GIM + goff;
    size_t ooff = (size_t)b * LSEQ * KP + p;

    float xr = 0.f, xi = 0.f;
    #pragma unroll 4
    for (int l = 0; l < LSEQ; l++) {
        float ur = gr[(size_t)l * PD];
        float ui = gi[(size_t)l * PD];
        float br = fmaf(cr, ur, -ci * ui);
        float bi = fmaf(cr, ui,  ci * ur);
        float nxr = fmaf(ar, xr, fmaf(-ai, xi, br));
        float nxi = fmaf(ar, xi, fmaf( ai, xr, bi));
        xr = nxr; xi = nxi;
        size_t o = ooff + (size_t)l * KP;
        __nv_bfloat16 h, lo;
        split_bf16(xr, h, lo); XRh[o] = h; XRl[o] = lo;
        split_bf16(xi, h, lo); XIh[o] = h; XIl[o] = lo;
    }
}

__global__ void padscan_kernel(__nv_bfloat16* p0, __nv_bfloat16* p1,
                               __nv_bfloat16* p2, __nv_bfloat16* p3)
{
    int i = blockIdx.x * blockDim.x + threadIdx.x;
    const int PADW = KP - DM;
    if (i >= MROWS * PADW) return;
    int r = i / PADW, c = DM + i % PADW;
    size_t idx = (size_t)r * KP + c;
    __nv_bfloat16 z = __float2bfloat16(0.f);
    p0[idx] = z; p1[idx] = z; p2[idx] = z; p3[idx] = z;
}

__global__ void geglu_kernel(const float* __restrict__ H2,
                             __nv_bfloat16* __restrict__ Th,
                             __nv_bfloat16* __restrict__ Tl)
{
    size_t i = (size_t)blockIdx.x * blockDim.x + threadIdx.x;
    if (i >= (size_t)MROWS * KP) return;
    int d = (int)(i % KP);
    size_t m = i / KP;
    if (d < DM) {
        const float* r = H2 + m * (size_t)(2 * DM);
        float v = r[d] * gelu_exact(r[DM + d]);
        __nv_bfloat16 h, l; split_bf16(v, h, l);
        Th[i] = h; Tl[i] = l;
    } else {
        Th[i] = __float2bfloat16(0.f);
        Tl[i] = __float2bfloat16(0.f);
    }
}

__global__ void addres_kernel(float* __restrict__ H, const float* __restrict__ Z,
                              const __nv_bfloat16* __restrict__ FYh,
                              const __nv_bfloat16* __restrict__ FYl)
{
    size_t i = (size_t)blockIdx.x * blockDim.x + threadIdx.x;
    if (i >= MD) return;
    int d = (int)(i % DM);
    size_t m = i / DM;
    size_t j = m * KP + d;
    H[i] += Z[i] + __bfloat162float(FYh[j]) + __bfloat162float(FYl[j]);
}

__global__ void convw_layer_kernel(
    const float* __restrict__ Bre, const float* __restrict__ Bim,
    const float* __restrict__ Cre, const float* __restrict__ Cim,
    const float* __restrict__ Wd,  const float* __restrict__ We,
    __nv_bfloat16* __restrict__ L)
{
    const size_t W1E = (size_t)NP1 * KP;
    const size_t W2E = (size_t)NP2 * KP;
    int w = blockIdx.y;
    const float* src; __nv_bfloat16 *Wh, *Wl; int N; size_t tot;
    switch (w) {
        case 0: src = Bre; Wh = L;          Wl = L + 1*W1E; N = PD;   tot = W1E; break;
        case 1: src = Bim; Wh = L + 2*W1E;  Wl = L + 3*W1E; N = PD;   tot = W1E; break;
        case 2: src = Cre; Wh = L + 4*W1E;  Wl = L + 5*W1E; N = DM;   tot = W1E; break;
        case 3: src = Cim; Wh = L + 6*W1E;  Wl = L + 7*W1E; N = DM;   tot = W1E; break;
        case 4: src = Wd;  Wh = L + 8*W1E;  Wl = L + 9*W1E; N = DM;   tot = W1E; break;
        default:src = We;  Wh = L + 10*W1E; Wl = L + 10*W1E + W2E; N = 2*DM; tot = W2E; break;
    }
    size_t i = (size_t)blockIdx.x * blockDim.x + threadIdx.x;
    if (i >= tot) return;
    int n = (int)(i / KP), k = (int)(i % KP);
    float v = (n < N && k < DM) ? src[(size_t)n * DM + k] : 0.f;
    __nv_bfloat16 h, l; split_bf16(v, h, l);
    Wh[i] = h; Wl[i] = l;
}

__global__ void zero_kernel(float* __restrict__ P, int n)
{
    int i = blockIdx.x * blockDim.x + threadIdx.x;
    if (i < n) P[i] = 0.f;
}

#define POOL_CHUNKS 32
__global__ void pool_kernel(const float* __restrict__ H, float* __restrict__ POOL)
{
    int t = blockIdx.x * blockDim.x + threadIdx.x;
    if (t >= BSZ * DM) return;
    int b = t / DM, d = t % DM;
    const int CL = LSEQ / POOL_CHUNKS;
    int l0 = blockIdx.y * CL;
    const float* h = H + (size_t)b * LSEQ * DM + (size_t)l0 * DM + d;
    float s = 0.f;
    #pragma unroll 8
    for (int l = 0; l < CL; l++) s += h[(size_t)l * DM];
    atomicAdd(&POOL[t], s);
}

__global__ void head_kernel(const float* __restrict__ POOL,
                            const float* __restrict__ hw,
                            const float* __restrict__ hb,
                            float* __restrict__ out)
{
    int b = blockIdx.x;
    int tid = threadIdx.x;
    __shared__ float sA[256];
    float s = 0.f;
    for (int d = tid; d < DM; d += 256) s = fmaf(POOL[b * DM + d], hw[d], s);
    sA[tid] = s; __syncthreads();
    for (int st = 128; st > 0; st >>= 1) {
        if (tid < st) sA[tid] += sA[tid + st];
        __syncthreads();
    }
    if (tid == 0) out[b] = sA[0] * (1.0f / LSEQ) + hb[0];
}

// ---------------------------------------------------------------------------
// kernel_launch
// ---------------------------------------------------------------------------
extern "C" void kernel_launch(void* const* d_in, const int* in_sizes, int n_in,
                              void* d_out, int out_size)
{
    const float* x           = (const float*)d_in[0];
    const float* enc_w       = (const float*)d_in[1];
    const float* enc_b       = (const float*)d_in[2];
    const float* norm_w      = (const float*)d_in[3];
    const float* norm_b      = (const float*)d_in[4];
    const float* attn_norm_w = (const float*)d_in[5];
    const float* attn_norm_b = (const float*)d_in[6];
    const float* ff_norm_w   = (const float*)d_in[7];
    const float* ff_norm_b   = (const float*)d_in[8];
    const float* lam_re      = (const float*)d_in[9];
    const float* lam_im      = (const float*)d_in[10];
    const float* log_step    = (const float*)d_in[11];
    const float* B_re        = (const float*)d_in[12];
    const float* B_im        = (const float*)d_in[13];
    const float* C_re        = (const float*)d_in[14];
    const float* C_im        = (const float*)d_in[15];
    const float* Dvec        = (const float*)d_in[16];
    const float* Wenc        = (const float*)d_in[17];
    const float* Wdec        = (const float*)d_in[18];
    const float* head_w      = (const float*)d_in[19];
    const float* head_b      = (const float*)d_in[20];
    float* out = (float*)d_out;

    float* base = nullptr;
    cudaGetSymbolAddress((void**)&base, g_scratch);

    float* H    = base + OFF_H;
    float* GRE  = base + OFF_GRE;
    float* GIM  = base + OFF_GIM;
    float* Y    = base + OFF_Y;
    float* Z    = base + OFF_Z;
    float* H2   = base + OFF_H2;
    float* POOL = base + OFF_POOL;

    __nv_bfloat16* actb = (__nv_bfloat16*)(base + OFF_ACT);
    const size_t AE = (size_t)MROWS * KP;
    __nv_bfloat16* FXh = actb + 0 * AE;
    __nv_bfloat16* FXl = actb + 1 * AE;
    __nv_bfloat16* XRh = actb + 2 * AE;
    __nv_bfloat16* XRl = actb + 3 * AE;
    __nv_bfloat16* XIh = actb + 4 * AE;
    __nv_bfloat16* XIl = actb + 5 * AE;
    __nv_bfloat16* FYh = actb + 6 * AE;
    __nv_bfloat16* FYl = actb + 7 * AE;
    __nv_bfloat16* Th  = actb + 8 * AE;
    __nv_bfloat16* Tl  = actb + 9 * AE;

    __nv_bfloat16* wb = (__nv_bfloat16*)(base + OFF_WB);
    const size_t W1E = (size_t)NP1 * KP;
    const size_t W2E = (size_t)NP2 * KP;
    const size_t WLE = 10 * W1E + 2 * W2E;

    cudaFuncSetAttribute(gemm_bf16x3, cudaFuncAttributeMaxDynamicSharedMemorySize,
                         GEMM_SMEM_BYTES);

    const int EW_BLOCKS = (int)((MD + 255) / 256);

    enc_kernel<<<EW_BLOCKS, 256>>>(x, enc_w, enc_b, H);   // 1

    {
        dim3 gw((unsigned)((W2E + 255) / 256), 6);
        for (int i = 0; i < NLAYERS; i++) {               // 2,3,4
            convw_layer_kernel<<<gw, 256>>>(
                B_re + (size_t)i*PD*DM, B_im + (size_t)i*PD*DM,
                C_re + (size_t)i*DM*PD, C_im + (size_t)i*DM*PD,
                Wdec + (size_t)i*DM*DM, Wenc + (size_t)i*2*DM*DM,
                wb + (size_t)i * WLE);
        }
    }

    dim3 g9(NP1 / 128, MROWS / 128);
    dim3 g17(NP2 / 128, MROWS / 128);
    bool padded = false;

    for (int i = 0; i < NLAYERS; i++) {
        const float* nw  = norm_w      + (size_t)i * DM;
        const float* nb  = norm_b      + (size_t)i * DM;
        const float* aw  = attn_norm_w + (size_t)i * DM;
        const float* ab  = attn_norm_b + (size_t)i * DM;
        const float* fw  = ff_norm_w   + (size_t)i * DM;
        const float* fb  = ff_norm_b   + (size_t)i * DM;
        const float* lre = lam_re      + (size_t)i * PD;
        const float* lim = lam_im      + (size_t)i * PD;
        const float* lst = log_step    + (size_t)i * PD;
        const float* dv  = Dvec        + (size_t)i * DM;

        __nv_bfloat16* L = wb + (size_t)i * WLE;
        __nv_bfloat16* Breh = L;             __nv_bfloat16* Brel = L + 1*W1E;
        __nv_bfloat16* Bimh = L + 2*W1E;     __nv_bfloat16* Biml = L + 3*W1E;
        __nv_bfloat16* Creh = L + 4*W1E;     __nv_bfloat16* Crel = L + 5*W1E;
        __nv_bfloat16* Cimh = L + 6*W1E;     __nv_bfloat16* Ciml = L + 7*W1E;
        __nv_bfloat16* Wdh  = L + 8*W1E;     __nv_bfloat16* Wdl  = L + 9*W1E;
        __nv_bfloat16* Weh  = L + 10*W1E;    __nv_bfloat16* Wel  = L + 10*W1E + W2E;

        ln2_kernel<<<MROWS, 256>>>(H, FXh, FXl, nw, nb, aw, ab);   // 5 (i=0)

        gemm_bf16x3<<<g9, 256, GEMM_SMEM_BYTES>>>(FXh, FXl, Breh, Brel, GRE, PD, 1.f, 0.f); // 6!
        gemm_bf16x3<<<g9, 256, GEMM_SMEM_BYTES>>>(FXh, FXl, Bimh, Biml, GIM, PD, 1.f, 0.f);

        if (!padded) {
            int npad = MROWS * (KP - DM);
            padscan_kernel<<<(npad + 255) / 256, 256>>>(XRh, XRl, XIh, XIl);
            padded = true;
        }

        scan_kernel<<<(BSZ * PD + 127) / 128, 128>>>(GRE, GIM, XRh, XRl, XIh, XIl,
                                                     lre, lim, lst);

        gemm_bf16x3<<<g9, 256, GEMM_SMEM_BYTES>>>(XRh, XRl, Creh, Crel, Y, DM, 1.f, 0.f);
        gemm_bf16x3<<<g9, 256, GEMM_SMEM_BYTES>>>(XIh, XIl, Cimh, Ciml, Y, DM, -1.f, 1.f);

        postln_kernel<<<MROWS, 256>>>(Y, FXh, FXl, dv, fw, fb, FYh, FYl);

        gemm_bf16x3<<<g17, 256, GEMM_SMEM_BYTES>>>(FYh, FYl, Weh, Wel, H2, 2 * DM, 1.f, 0.f);

        {
            size_t n = (size_t)MROWS * KP;
            geglu_kernel<<<(int)((n + 255) / 256), 256>>>(H2, Th, Tl);
        }

        gemm_bf16x3<<<g9, 256, GEMM_SMEM_BYTES>>>(Th, Tl, Wdh, Wdl, Z, DM, 1.f, 0.f);

        addres_kernel<<<EW_BLOCKS, 256>>>(H, Z, FYh, FYl);
    }

    zero_kernel<<<(BSZ * DM + 255) / 256, 256>>>(POOL, BSZ * DM);
    dim3 gp((BSZ * DM + 127) / 128, POOL_CHUNKS);
    pool_kernel<<<gp, 128>>>(H, POOL);
    head_kernel<<<BSZ, 256>>>(POOL, head_w, head_b, out);
}

// round 9
// speedup vs baseline: 2.9849x; 1.3709x over previous
#include <cuda_runtime.h>
#include <cuda_bf16.h>
#include <math.h>
#include <cstdint>

// ---------------------------------------------------------------------------
// Problem constants
// ---------------------------------------------------------------------------
#define BSZ     4
#define LSEQ    4096
#define DM      1048
#define PD      1048
#define NLAYERS 3
#define MROWS   (BSZ*LSEQ)              // 16384
#define MD      ((size_t)MROWS * DM)
#define KP      1088                    // K padded to multiple of 64
#define NCHUNK  (KP/64)                 // 17
#define NP1     1152
#define NP2     2176

#define MD_F   17170432ULL
#define ACT_F  8912896ULL
#define W1_F   626688ULL
#define W2_F   1183744ULL
#define WL_F   (10ULL*W1_F + 2ULL*W2_F)

#define OFF_H    0ULL
#define OFF_GRE  (1ULL*MD_F)
#define OFF_GIM  (2ULL*MD_F)
#define OFF_Y    (3ULL*MD_F)
#define OFF_Z    (4ULL*MD_F)
#define OFF_H2   (5ULL*MD_F)
#define OFF_ACT  (7ULL*MD_F)
#define OFF_WB   (OFF_ACT + 10ULL*ACT_F)
#define OFF_POOL (OFF_WB + 3ULL*WL_F)
#define TOT_F    (OFF_POOL + 8192ULL)

__device__ __align__(1024) float g_scratch[TOT_F];

#if defined(__CUDA_ARCH_FEAT_SM103_ALL) || defined(__CUDA_ARCH_SPECIFIC__) || defined(__CUDA_ARCH_FEAT_SM100_ALL)
#define HAS_TCGEN05 1
#else
#define HAS_TCGEN05 0
#endif

__device__ __forceinline__ float gelu_exact(float x) {
    return 0.5f * x * (1.0f + erff(x * 0.70710678118654752f));
}

__device__ __forceinline__ uint32_t smem_u32_of(const void* p) {
    uint32_t a;
    asm("{ .reg .u64 t; cvta.to.shared.u64 t, %1; cvt.u32.u64 %0, t; }"
        : "=r"(a) : "l"(p));
    return a;
}

__device__ __forceinline__ void split_bf16(float v, __nv_bfloat16& h, __nv_bfloat16& l) {
    h = __float2bfloat16(v);
    l = __float2bfloat16(v - __bfloat162float(h));
}

__device__ __forceinline__ uint32_t elect_one_pred() {
    uint32_t pred;
    asm volatile(
        "{\n\t.reg .pred p;\n\telect.sync _|p, 0xFFFFFFFF;\n\t"
        "selp.b32 %0, 1, 0, p;\n\t}" : "=r"(pred));
    return pred;
}

// ---------------------------------------------------------------------------
// Shared PTX macros
// ---------------------------------------------------------------------------
#define CP_ASYNC_16(saddr, gptr) \
    asm volatile("cp.async.cg.shared.global [%0], [%1], 16;" \
        :: "r"(saddr), "l"(gptr) : "memory")
#define CP_COMMIT() asm volatile("cp.async.commit_group;" ::: "memory")
#define CP_WAIT_GROUP_1() asm volatile("cp.async.wait_group 1;" ::: "memory")
// .noinc is load-bearing: without it each arrive first increments the pending
// count (self-balancing), so a count-256 barrier never completes -> deadlock.
#define CP_ASYNC_MBAR_ARRIVE_NOINC(mbar) \
    asm volatile("cp.async.mbarrier.arrive.noinc.shared::cta.b64 [%0];" \
        :: "r"((uint32_t)(mbar)) : "memory")

#define LDMATRIX_X4(r0, r1, r2, r3, addr) \
    asm volatile("ldmatrix.sync.aligned.m8n8.x4.shared.b16 {%0,%1,%2,%3}, [%4];" \
        : "=r"(r0), "=r"(r1), "=r"(r2), "=r"(r3) : "r"(addr))

#define MMA_BF16(c, a, b0, b1) \
    asm volatile("mma.sync.aligned.m16n8k16.row.col.f32.bf16.bf16.f32 " \
        "{%0,%1,%2,%3},{%4,%5,%6,%7},{%8,%9},{%0,%1,%2,%3};" \
        : "+f"((c)[0]), "+f"((c)[1]), "+f"((c)[2]), "+f"((c)[3]) \
        : "r"((a)[0]), "r"((a)[1]), "r"((a)[2]), "r"((a)[3]), "r"(b0), "r"(b1))

#define MBARRIER_INIT(mbar, count) \
    asm volatile("mbarrier.init.shared.b64 [%0], %1;" \
        :: "r"((uint32_t)(mbar)), "r"((uint32_t)(count)) : "memory")
#define MBARRIER_WAIT_PARITY(mbar, parity) do { \
    uint32_t _mbar = (uint32_t)(mbar); \
    uint32_t _parity = (uint32_t)(parity); \
    uint32_t _done; \
    asm volatile( \
        "{\n\t.reg .pred p;\n\t" \
        "mbarrier.try_wait.parity.acquire.cta.shared::cta.b64 p, [%1], %2;\n\t" \
        "selp.b32 %0, 1, 0, p;\n\t}" \
        : "=r"(_done) : "r"(_mbar), "r"(_parity) : "memory"); \
    if (!_done) { \
        asm volatile( \
            "{\n\t.reg .pred P1;\n\t" \
            "WAIT_LOOP_%=:\n\t" \
            "mbarrier.try_wait.parity.acquire.cta.shared::cta.b64 P1, [%0], %1, 0x989680;\n\t" \
            "@P1 bra.uni WAIT_DONE_%=;\n\t" \
            "bra.uni WAIT_LOOP_%=;\n\t" \
            "WAIT_DONE_%=:\n\t}" \
            :: "r"(_mbar), "r"(_parity) : "memory"); \
    } \
} while(0)

#define GEMM_SMEM_BYTES 221184

#if HAS_TCGEN05
// ===== tcgen05 path: decoupled mbarrier pipeline =============================
#define TCGEN05_ALLOC(saddr, nCols) \
    asm volatile("tcgen05.alloc.cta_group::1.sync.aligned.shared::cta.b32 [%0], %1;" \
        :: "r"((uint32_t)(saddr)), "r"((uint32_t)(nCols)) : "memory")
#define TCGEN05_DEALLOC(tmem, nCols) \
    asm volatile("tcgen05.dealloc.cta_group::1.sync.aligned.b32 %0, %1;" \
        :: "r"(tmem), "r"((uint32_t)(nCols)))
#define TCGEN05_RELINQUISH() \
    asm volatile("tcgen05.relinquish_alloc_permit.cta_group::1.sync.aligned;")
#define TCGEN05_COMMIT(mbar) \
    asm volatile("tcgen05.commit.cta_group::1.mbarrier::arrive::one.shared::cluster.b64 [%0];" \
        :: "r"((uint32_t)(mbar)) : "memory")
#define TCGEN05_FENCE_AFTER() \
    asm volatile("tcgen05.fence::after_thread_sync;" ::: "memory")
#define TCGEN05_WAIT_LD() \
    asm volatile("tcgen05.wait::ld.sync.aligned;" ::: "memory")
#define FENCE_PROXY_ASYNC() \
    asm volatile("fence.proxy.async.shared::cta;" ::: "memory")
#define TCGEN05_LD_32X32B_X32(r, taddr) \
    asm volatile( \
        "tcgen05.ld.sync.aligned.32x32b.x32.b32 " \
        "{%0, %1, %2, %3, %4, %5, %6, %7, " \
        " %8, %9, %10, %11, %12, %13, %14, %15, " \
        " %16, %17, %18, %19, %20, %21, %22, %23, " \
        " %24, %25, %26, %27, %28, %29, %30, %31}, [%32];" \
        : "=r"((r)[0]),  "=r"((r)[1]),  "=r"((r)[2]),  "=r"((r)[3]), \
          "=r"((r)[4]),  "=r"((r)[5]),  "=r"((r)[6]),  "=r"((r)[7]), \
          "=r"((r)[8]),  "=r"((r)[9]),  "=r"((r)[10]), "=r"((r)[11]), \
          "=r"((r)[12]), "=r"((r)[13]), "=r"((r)[14]), "=r"((r)[15]), \
          "=r"((r)[16]), "=r"((r)[17]), "=r"((r)[18]), "=r"((r)[19]), \
          "=r"((r)[20]), "=r"((r)[21]), "=r"((r)[22]), "=r"((r)[23]), \
          "=r"((r)[24]), "=r"((r)[25]), "=r"((r)[26]), "=r"((r)[27]), \
          "=r"((r)[28]), "=r"((r)[29]), "=r"((r)[30]), "=r"((r)[31]) \
        : "r"(taddr))

static constexpr uint64_t SMEM_DESC_BASE_SW128 =
    (uint64_t(2) << 61) | (uint64_t(1) << 46) | (uint64_t(64) << 32) | (uint64_t(1) << 16);
#define MAKE_SMEM_DESC(base_addr) \
    (SMEM_DESC_BASE_SW128 | ((uint64_t)((base_addr) >> 4) & 0x3FFF))

static constexpr uint32_t GIDESC =
    (1u<<4) | (1u<<7) | (1u<<10) | ((128u/8u)<<17) | ((128u/16u)<<24);

__device__ __forceinline__ void mma_f16_ss(uint32_t d_tmem, uint64_t a_desc,
                                           uint64_t b_desc, uint32_t en) {
    asm volatile(
        "{\n\t.reg .pred p;\n\tsetp.ne.u32 p, %4, 0;\n\t"
        "tcgen05.mma.cta_group::1.kind::f16 [%0], %1, %2, %3, {%5, %5, %5, %5}, p;\n\t}"
        :: "r"(d_tmem), "l"(a_desc), "l"(b_desc), "r"(GIDESC), "r"(en), "r"(0u)
        : "memory");
}

#define TPLANE 16384
#define TSTAGE 65536
// smem: [0] tmem ptr, [16..40) full[3], [40..64) done[3], data at 1024

__global__ __launch_bounds__(256) void gemm_bf16x3(
    const __nv_bfloat16* __restrict__ Ah, const __nv_bfloat16* __restrict__ Al,
    const __nv_bfloat16* __restrict__ Bh, const __nv_bfloat16* __restrict__ Bl,
    float* __restrict__ C, int N, float alpha, float beta)
{
    extern __shared__ __align__(1024) char smem[];
    const uint32_t sbase = smem_u32_of(smem);
    const int tid = threadIdx.x;
    const int wid = tid >> 5;
    const int lid = tid & 31;

    if (wid == 0) {
        TCGEN05_ALLOC(sbase + 0, 128);
        TCGEN05_RELINQUISH();
    }
    if (tid == 0) {
        #pragma unroll
        for (int s = 0; s < 3; s++) {
            MBARRIER_INIT(sbase + 16 + 8 * s, 256);  // full[s]: one arrive/thread
            MBARRIER_INIT(sbase + 40 + 8 * s, 1);    // done[s]: armed by commit
        }
    }
    __syncthreads();
    uint32_t tmem;
    asm volatile("ld.shared.b32 %0, [%1];" : "=r"(tmem) : "r"(sbase));

    const __nv_bfloat16* srcs[4];
    srcs[0] = Ah + (size_t)blockIdx.y * 128 * KP;
    srcs[1] = Al + (size_t)blockIdx.y * 128 * KP;
    srcs[2] = Bh + (size_t)blockIdx.x * 128 * KP;
    srcs[3] = Bl + (size_t)blockIdx.x * 128 * KP;

    // prefetch one chunk into stage kc%3; arm full[s] via this thread's
    // cp.async completion (noinc). SW128 swizzle at 16B: j -> j^(r&7).
    auto prefetch = [&](int kc) {
        const int s = kc % 3;
        const int k0 = kc * 64;
        const uint32_t stb = sbase + 1024 + s * TSTAGE;
        #pragma unroll
        for (int i = 0; i < 16; i++) {
            int c  = i * 256 + tid;
            int pl = c >> 10;
            int r  = (c >> 3) & 127;
            int j  = c & 7;
            uint32_t dst = stb + pl * TPLANE + r * 128 + ((j ^ (r & 7)) << 4);
            CP_ASYNC_16(dst, srcs[pl] + (size_t)r * KP + k0 + j * 8);
        }
        CP_ASYNC_MBAR_ARRIVE_NOINC(sbase + 16 + 8 * s);
    };

    const uint32_t ismma = (wid == 0) ? elect_one_pred() : 0u;

    prefetch(0);
    prefetch(1);
    prefetch(2);

    for (int kc = 0; kc < NCHUNK; kc++) {
        const int s = kc % 3;
        const uint32_t ph = (kc / 3) & 1;

        if (ismma) {
            MBARRIER_WAIT_PARITY(sbase + 16 + 8 * s, ph);
            FENCE_PROXY_ASYNC();
            const uint32_t stb = sbase + 1024 + s * TSTAGE;
            uint64_t dAh = MAKE_SMEM_DESC(stb);
            uint64_t dAl = MAKE_SMEM_DESC(stb + TPLANE);
            uint64_t dBh = MAKE_SMEM_DESC(stb + 2 * TPLANE);
            uint64_t dBl = MAKE_SMEM_DESC(stb + 3 * TPLANE);
            #pragma unroll
            for (int ks = 0; ks < 4; ks++) {
                mma_f16_ss(tmem, dAh + ks * 2, dBh + ks * 2, (kc != 0) || (ks != 0));
                mma_f16_ss(tmem, dAh + ks * 2, dBl + ks * 2, 1u);
                mma_f16_ss(tmem, dAl + ks * 2, dBh + ks * 2, 1u);
            }
            TCGEN05_COMMIT(sbase + 40 + 8 * s);
        }

        if (kc + 3 < NCHUNK) {
            // stage s reused by chunk kc+3; wait until chunk kc's MMAs drained
            MBARRIER_WAIT_PARITY(sbase + 40 + 8 * s, ph);
            prefetch(kc + 3);
        }
    }

    if (ismma) {
        int pc = NCHUNK - 1;
        MBARRIER_WAIT_PARITY(sbase + 40 + 8 * (pc % 3), (pc / 3) & 1);
    }
    __syncthreads();
    TCGEN05_FENCE_AFTER();

    // epilogue: warps 0-3 read TMEM, vectorized stores
    if (wid < 4) {
        const int nbase = blockIdx.x * 128;
        const size_t m = (size_t)blockIdx.y * 128 + wid * 32 + lid;
        float* crow = C + m * (size_t)N;
        for (int cb = 0; cb < 4; cb++) {
            uint32_t r[32];
            TCGEN05_LD_32X32B_X32(r, tmem + cb * 32);
            TCGEN05_WAIT_LD();
            #pragma unroll
            for (int c = 0; c < 32; c += 4) {
                int n = nbase + cb * 32 + c;
                if (n + 3 < N) {
                    float4 v;
                    v.x = alpha * __uint_as_float(r[c + 0]);
                    v.y = alpha * __uint_as_float(r[c + 1]);
                    v.z = alpha * __uint_as_float(r[c + 2]);
                    v.w = alpha * __uint_as_float(r[c + 3]);
                    if (beta != 0.f) {
                        float4 o = *reinterpret_cast<const float4*>(crow + n);
                        v.x = fmaf(beta, o.x, v.x);
                        v.y = fmaf(beta, o.y, v.y);
                        v.z = fmaf(beta, o.z, v.z);
                        v.w = fmaf(beta, o.w, v.w);
                    }
                    *reinterpret_cast<float4*>(crow + n) = v;
                } else {
                    for (int q = 0; q < 4; q++) {
                        int nn = n + q;
                        if (nn < N) {
                            float v = alpha * __uint_as_float(r[c + q]);
                            if (beta != 0.f) v = fmaf(beta, crow[nn], v);
                            crow[nn] = v;
                        }
                    }
                }
            }
        }
    }
    __syncthreads();
    if (wid == 0) TCGEN05_DEALLOC(tmem, 128);
}

#else
// ===== mma.sync fallback (generic pass; never runs on sm_103a) ==============
#define ROWB    144
#define PLANEB  (128*ROWB)
#define STAGEB  (4*PLANEB)

__global__ __launch_bounds__(256) void gemm_bf16x3(
    const __nv_bfloat16* __restrict__ Ah, const __nv_bfloat16* __restrict__ Al,
    const __nv_bfloat16* __restrict__ Bh, const __nv_bfloat16* __restrict__ Bl,
    float* __restrict__ C, int N, float alpha, float beta)
{
    extern __shared__ __align__(128) char smem[];
    const uint32_t sbase = smem_u32_of(smem);
    const int tid = threadIdx.x;
    const int wid = tid >> 5;
    const int lid = tid & 31;
    const int wm  = wid & 1;
    const int wn  = wid >> 1;

    const __nv_bfloat16* srcs[4];
    srcs[0] = Ah + (size_t)blockIdx.y * 128 * KP;
    srcs[1] = Al + (size_t)blockIdx.y * 128 * KP;
    srcs[2] = Bh + (size_t)blockIdx.x * 128 * KP;
    srcs[3] = Bl + (size_t)blockIdx.x * 128 * KP;

    auto prefetch = [&](int kc, int stage) {
        const int k0 = kc * 64;
        const uint32_t stb = sbase + stage * STAGEB;
        #pragma unroll
        for (int i = 0; i < 16; i++) {
            int c = i * 256 + tid;
            int pl = c >> 10;
            int r  = (c >> 3) & 127;
            int col = c & 7;
            CP_ASYNC_16(stb + pl * PLANEB + r * ROWB + col * 16,
                        srcs[pl] + (size_t)r * KP + k0 + col * 8);
        }
    };

    float acc[4][4][4];
    #pragma unroll
    for (int i = 0; i < 4; i++)
        #pragma unroll
        for (int j = 0; j < 4; j++)
            #pragma unroll
            for (int k = 0; k < 4; k++) acc[i][j][k] = 0.f;

    prefetch(0, 0); CP_COMMIT();
    prefetch(1, 1); CP_COMMIT();

    const int lrow = lid & 15;
    const int lcol = (lid >> 4) << 4;

    for (int kc = 0; kc < NCHUNK; kc++) {
        CP_WAIT_GROUP_1();
        __syncthreads();
        if (kc + 2 < NCHUNK) prefetch(kc + 2, (kc + 2) % 3);
        CP_COMMIT();

        const uint32_t stb = sbase + (kc % 3) * STAGEB;
        const uint32_t aHb = stb;
        const uint32_t aLb = stb + PLANEB;
        const uint32_t bHb = stb + 2 * PLANEB;
        const uint32_t bLb = stb + 3 * PLANEB;

        #pragma unroll
        for (int ks = 0; ks < 4; ks++) {
            uint32_t ah[4][4], al[4][4], bh[2][4], bl[2][4];
            #pragma unroll
            for (int mb = 0; mb < 4; mb++) {
                uint32_t off = (uint32_t)((wm * 64 + mb * 16 + lrow) * ROWB + ks * 32 + lcol);
                LDMATRIX_X4(ah[mb][0], ah[mb][1], ah[mb][2], ah[mb][3], aHb + off);
                LDMATRIX_X4(al[mb][0], al[mb][1], al[mb][2], al[mb][3], aLb + off);
            }
            #pragma unroll
            for (int p = 0; p < 2; p++) {
                uint32_t off = (uint32_t)((wn * 32 + p * 16 + lrow) * ROWB + ks * 32 + lcol);
                LDMATRIX_X4(bh[p][0], bh[p][1], bh[p][2], bh[p][3], bHb + off);
                LDMATRIX_X4(bl[p][0], bl[p][1], bl[p][2], bl[p][3], bLb + off);
            }
            #pragma unroll
            for (int mb = 0; mb < 4; mb++) {
                #pragma unroll
                for (int nb = 0; nb < 4; nb++) {
                    uint32_t b0h = bh[nb >> 1][(nb & 1)];
                    uint32_t b1h = bh[nb >> 1][(nb & 1) + 2];
                    uint32_t b0l = bl[nb >> 1][(nb & 1)];
                    uint32_t b1l = bl[nb >> 1][(nb & 1) + 2];
                    MMA_BF16(acc[mb][nb], ah[mb], b0h, b1h);
                    MMA_BF16(acc[mb][nb], ah[mb], b0l, b1l);
                    MMA_BF16(acc[mb][nb], al[mb], b0h, b1h);
                }
            }
        }
    }

    const int tig = lid & 3;
    const int grp = lid >> 2;
    const int mBase = blockIdx.y * 128 + wm * 64;
    const int nBase = blockIdx.x * 128 + wn * 32;
    #pragma unroll
    for (int mb = 0; mb < 4; mb++) {
        #pragma unroll
        for (int nb = 0; nb < 4; nb++) {
            int n = nBase + nb * 8 + tig * 2;
            if (n >= N) continue;
            int m0 = mBase + mb * 16 + grp;
            size_t i0 = (size_t)m0 * N + n;
            size_t i1 = (size_t)(m0 + 8) * N + n;
            float v0 = alpha * acc[mb][nb][0];
            float v1 = alpha * acc[mb][nb][1];
            float v2 = alpha * acc[mb][nb][2];
            float v3 = alpha * acc[mb][nb][3];
            if (beta != 0.f) {
                v0 = fmaf(beta, C[i0], v0);
                v1 = fmaf(beta, C[i0 + 1], v1);
                v2 = fmaf(beta, C[i1], v2);
                v3 = fmaf(beta, C[i1 + 1], v3);
            }
            *reinterpret_cast<float2*>(C + i0) = make_float2(v0, v1);
            *reinterpret_cast<float2*>(C + i1) = make_float2(v2, v3);
        }
    }
}
#endif

// ---------------------------------------------------------------------------
// Elementwise / row kernels
// ---------------------------------------------------------------------------
__global__ void enc_kernel(const float* __restrict__ x,
                           const float* __restrict__ ew,
                           const float* __restrict__ eb,
                           float* __restrict__ H)
{
    size_t i = (size_t)blockIdx.x * blockDim.x + threadIdx.x;
    if (i >= MD) return;
    int d = (int)(i % DM);
    int m = (int)(i / DM);
    H[i] = fmaf(x[m], ew[d], eb[d]);
}

__global__ __launch_bounds__(256) void ln2_kernel(
    const float* __restrict__ X,
    __nv_bfloat16* __restrict__ Oh, __nv_bfloat16* __restrict__ Ol,
    const float* __restrict__ w1, const float* __restrict__ b1,
    const float* __restrict__ w2, const float* __restrict__ b2)
{
    const int row = blockIdx.x;
    const int tid = threadIdx.x;
    const float* x = X + (size_t)row * DM;
    const size_t ro = (size_t)row * KP;
    __shared__ float sA[256], sB[256];

    float v[5];
    float s = 0.f, ss = 0.f;
    #pragma unroll
    for (int k = 0; k < 5; k++) {
        int d = tid + k * 256;
        float t = (d < DM) ? x[d] : 0.f;
        v[k] = t; s += t; ss += t * t;
    }
    sA[tid] = s; sB[tid] = ss; __syncthreads();
    for (int st = 128; st > 0; st >>= 1) {
        if (tid < st) { sA[tid] += sA[tid + st]; sB[tid] += sB[tid + st]; }
        __syncthreads();
    }
    float mu  = sA[0] * (1.0f / DM);
    float var = sB[0] * (1.0f / DM) - mu * mu;
    float rs  = rsqrtf(var + 1e-5f);
    __syncthreads();

    s = 0.f; ss = 0.f;
    #pragma unroll
    for (int k = 0; k < 5; k++) {
        int d = tid + k * 256;
        float r = 0.f;
        if (d < DM) r = fmaf((v[k] - mu) * rs, w1[d], b1[d]);
        v[k] = r; s += r; ss += r * r;
    }
    sA[tid] = s; sB[tid] = ss; __syncthreads();
    for (int st = 128; st > 0; st >>= 1) {
        if (tid < st) { sA[tid] += sA[tid + st]; sB[tid] += sB[tid + st]; }
        __syncthreads();
    }
    float mu2  = sA[0] * (1.0f / DM);
    float var2 = sB[0] * (1.0f / DM) - mu2 * mu2;
    float rs2  = rsqrtf(var2 + 1e-5f);
    #pragma unroll
    for (int k = 0; k < 5; k++) {
        int d = tid + k * 256;
        if (d < DM) {
            float r2 = fmaf((v[k] - mu2) * rs2, w2[d], b2[d]);
            __nv_bfloat16 h, l; split_bf16(r2, h, l);
            Oh[ro + d] = h; Ol[ro + d] = l;
        } else if (d < KP) {
            Oh[ro + d] = __float2bfloat16(0.f);
            Ol[ro + d] = __float2bfloat16(0.f);
        }
    }
}

__global__ __launch_bounds__(256) void postln_kernel(
    const float* __restrict__ Y,
    const __nv_bfloat16* __restrict__ FXh, const __nv_bfloat16* __restrict__ FXl,
    const float* __restrict__ dv,
    const float* __restrict__ w, const float* __restrict__ b,
    __nv_bfloat16* __restrict__ Oh, __nv_bfloat16* __restrict__ Ol)
{
    const int row = blockIdx.x;
    const int tid = threadIdx.x;
    const float* y = Y + (size_t)row * DM;
    const size_t ro = (size_t)row * KP;
    __shared__ float sA[256], sB[256];

    float v[5];
    float s = 0.f, ss = 0.f;
    #pragma unroll
    for (int k = 0; k < 5; k++) {
        int d = tid + k * 256;
        float z = 0.f;
        if (d < DM) {
            float f = __bfloat162float(FXh[ro + d]) + __bfloat162float(FXl[ro + d]);
            float e = fmaf(dv[d], f, y[d]);
            z = gelu_exact(e) + f;
        }
        v[k] = z; s += z; ss += z * z;
    }
    sA[tid] = s; sB[tid] = ss; __syncthreads();
    for (int st = 128; st > 0; st >>= 1) {
        if (tid < st) { sA[tid] += sA[tid + st]; sB[tid] += sB[tid + st]; }
        __syncthreads();
    }
    float mu  = sA[0] * (1.0f / DM);
    float var = sB[0] * (1.0f / DM) - mu * mu;
    float rs  = rsqrtf(var + 1e-5f);
    #pragma unroll
    for (int k = 0; k < 5; k++) {
        int d = tid + k * 256;
        if (d < DM) {
            float r = fmaf((v[k] - mu) * rs, w[d], b[d]);
            __nv_bfloat16 h, l; split_bf16(r, h, l);
            Oh[ro + d] = h; Ol[ro + d] = l;
        } else if (d < KP) {
            Oh[ro + d] = __float2bfloat16(0.f);
            Ol[ro + d] = __float2bfloat16(0.f);
        }
    }
}

__global__ void scan_kernel(
    const float* __restrict__ GRE, const float* __restrict__ GIM,
    __nv_bfloat16* __restrict__ XRh, __nv_bfloat16* __restrict__ XRl,
    __nv_bfloat16* __restrict__ XIh, __nv_bfloat16* __restrict__ XIl,
    const float* __restrict__ lr_, const float* __restrict__ li_,
    const float* __restrict__ ls_)
{
    int t = blockIdx.x * blockDim.x + threadIdx.x;
    if (t >= BSZ * PD) return;
    int b = t / PD, p = t % PD;

    float lr = lr_[p], li = li_[p];
    float st = expf(ls_[p]);
    float er = expf(lr * st);
    float sn, cs; sincosf(li * st, &sn, &cs);
    float ar = er * cs, ai = er * sn;
    float inv = 1.0f / (lr * lr + li * li);
    float nr = ar - 1.0f;
    float cr = (nr * lr + ai * li) * inv;
    float ci = (ai * lr - nr * li) * inv;

    size_t goff = (size_t)b * LSEQ * PD + p;
    const float* gr = GRE + goff;
    const float* gi = GIM + goff;
    size_t ooff = (size_t)b * LSEQ * KP + p;

    float xr = 0.f, xi = 0.f;
    #pragma unroll 4
    for (int l = 0; l < LSEQ; l++) {
        float ur = gr[(size_t)l * PD];
        float ui = gi[(size_t)l * PD];
        float br = fmaf(cr, ur, -ci * ui);
        float bi = fmaf(cr, ui,  ci * ur);
        float nxr = fmaf(ar, xr, fmaf(-ai, xi, br));
        float nxi = fmaf(ar, xi, fmaf( ai, xr, bi));
        xr = nxr; xi = nxi;
        size_t o = ooff + (size_t)l * KP;
        __nv_bfloat16 h, lo;
        split_bf16(xr, h, lo); XRh[o] = h; XRl[o] = lo;
        split_bf16(xi, h, lo); XIh[o] = h; XIl[o] = lo;
    }
}

__global__ void padscan_kernel(__nv_bfloat16* p0, __nv_bfloat16* p1,
                               __nv_bfloat16* p2, __nv_bfloat16* p3)
{
    int i = blockIdx.x * blockDim.x + threadIdx.x;
    const int PADW = KP - DM;
    if (i >= MROWS * PADW) return;
    int r = i / PADW, c = DM + i % PADW;
    size_t idx = (size_t)r * KP + c;
    __nv_bfloat16 z = __float2bfloat16(0.f);
    p0[idx] = z; p1[idx] = z; p2[idx] = z; p3[idx] = z;
}

__global__ void geglu_kernel(const float* __restrict__ H2,
                             __nv_bfloat16* __restrict__ Th,
                             __nv_bfloat16* __restrict__ Tl)
{
    size_t i = (size_t)blockIdx.x * blockDim.x + threadIdx.x;
    if (i >= (size_t)MROWS * KP) return;
    int d = (int)(i % KP);
    size_t m = i / KP;
    if (d < DM) {
        const float* r = H2 + m * (size_t)(2 * DM);
        float v = r[d] * gelu_exact(r[DM + d]);
        __nv_bfloat16 h, l; split_bf16(v, h, l);
        Th[i] = h; Tl[i] = l;
    } else {
        Th[i] = __float2bfloat16(0.f);
        Tl[i] = __float2bfloat16(0.f);
    }
}

__global__ void addres_kernel(float* __restrict__ H, const float* __restrict__ Z,
                              const __nv_bfloat16* __restrict__ FYh,
                              const __nv_bfloat16* __restrict__ FYl)
{
    size_t i = (size_t)blockIdx.x * blockDim.x + threadIdx.x;
    if (i >= MD) return;
    int d = (int)(i % DM);
    size_t m = i / DM;
    size_t j = m * KP + d;
    H[i] += Z[i] + __bfloat162float(FYh[j]) + __bfloat162float(FYl[j]);
}

__global__ void convw_layer_kernel(
    const float* __restrict__ Bre, const float* __restrict__ Bim,
    const float* __restrict__ Cre, const float* __restrict__ Cim,
    const float* __restrict__ Wd,  const float* __restrict__ We,
    __nv_bfloat16* __restrict__ L)
{
    const size_t W1E = (size_t)NP1 * KP;
    const size_t W2E = (size_t)NP2 * KP;
    int w = blockIdx.y;
    const float* src; __nv_bfloat16 *Wh, *Wl; int N; size_t tot;
    switch (w) {
        case 0: src = Bre; Wh = L;          Wl = L + 1*W1E; N = PD;   tot = W1E; break;
        case 1: src = Bim; Wh = L + 2*W1E;  Wl = L + 3*W1E; N = PD;   tot = W1E; break;
        case 2: src = Cre; Wh = L + 4*W1E;  Wl = L + 5*W1E; N = DM;   tot = W1E; break;
        case 3: src = Cim; Wh = L + 6*W1E;  Wl = L + 7*W1E; N = DM;   tot = W1E; break;
        case 4: src = Wd;  Wh = L + 8*W1E;  Wl = L + 9*W1E; N = DM;   tot = W1E; break;
        default:src = We;  Wh = L + 10*W1E; Wl = L + 10*W1E + W2E; N = 2*DM; tot = W2E; break;
    }
    size_t i = (size_t)blockIdx.x * blockDim.x + threadIdx.x;
    if (i >= tot) return;
    int n = (int)(i / KP), k = (int)(i % KP);
    float v = (n < N && k < DM) ? src[(size_t)n * DM + k] : 0.f;
    __nv_bfloat16 h, l; split_bf16(v, h, l);
    Wh[i] = h; Wl[i] = l;
}

__global__ void zero_kernel(float* __restrict__ P, int n)
{
    int i = blockIdx.x * blockDim.x + threadIdx.x;
    if (i < n) P[i] = 0.f;
}

#define POOL_CHUNKS 32
__global__ void pool_kernel(const float* __restrict__ H, float* __restrict__ POOL)
{
    int t = blockIdx.x * blockDim.x + threadIdx.x;
    if (t >= BSZ * DM) return;
    int b = t / DM, d = t % DM;
    const int CL = LSEQ / POOL_CHUNKS;
    int l0 = blockIdx.y * CL;
    const float* h = H + (size_t)b * LSEQ * DM + (size_t)l0 * DM + d;
    float s = 0.f;
    #pragma unroll 8
    for (int l = 0; l < CL; l++) s += h[(size_t)l * DM];
    atomicAdd(&POOL[t], s);
}

__global__ void head_kernel(const float* __restrict__ POOL,
                            const float* __restrict__ hw,
                            const float* __restrict__ hb,
                            float* __restrict__ out)
{
    int b = blockIdx.x;
    int tid = threadIdx.x;
    __shared__ float sA[256];
    float s = 0.f;
    for (int d = tid; d < DM; d += 256) s = fmaf(POOL[b * DM + d], hw[d], s);
    sA[tid] = s; __syncthreads();
    for (int st = 128; st > 0; st >>= 1) {
        if (tid < st) sA[tid] += sA[tid + st];
        __syncthreads();
    }
    if (tid == 0) out[b] = sA[0] * (1.0f / LSEQ) + hb[0];
}

// ---------------------------------------------------------------------------
// kernel_launch
// ---------------------------------------------------------------------------
extern "C" void kernel_launch(void* const* d_in, const int* in_sizes, int n_in,
                              void* d_out, int out_size)
{
    const float* x           = (const float*)d_in[0];
    const float* enc_w       = (const float*)d_in[1];
    const float* enc_b       = (const float*)d_in[2];
    const float* norm_w      = (const float*)d_in[3];
    const float* norm_b      = (const float*)d_in[4];
    const float* attn_norm_w = (const float*)d_in[5];
    const float* attn_norm_b = (const float*)d_in[6];
    const float* ff_norm_w   = (const float*)d_in[7];
    const float* ff_norm_b   = (const float*)d_in[8];
    const float* lam_re      = (const float*)d_in[9];
    const float* lam_im      = (const float*)d_in[10];
    const float* log_step    = (const float*)d_in[11];
    const float* B_re        = (const float*)d_in[12];
    const float* B_im        = (const float*)d_in[13];
    const float* C_re        = (const float*)d_in[14];
    const float* C_im        = (const float*)d_in[15];
    const float* Dvec        = (const float*)d_in[16];
    const float* Wenc        = (const float*)d_in[17];
    const float* Wdec        = (const float*)d_in[18];
    const float* head_w      = (const float*)d_in[19];
    const float* head_b      = (const float*)d_in[20];
    float* out = (float*)d_out;

    float* base = nullptr;
    cudaGetSymbolAddress((void**)&base, g_scratch);

    float* H    = base + OFF_H;
    float* GRE  = base + OFF_GRE;
    float* GIM  = base + OFF_GIM;
    float* Y    = base + OFF_Y;
    float* Z    = base + OFF_Z;
    float* H2   = base + OFF_H2;
    float* POOL = base + OFF_POOL;

    __nv_bfloat16* actb = (__nv_bfloat16*)(base + OFF_ACT);
    const size_t AE = (size_t)MROWS * KP;
    __nv_bfloat16* FXh = actb + 0 * AE;
    __nv_bfloat16* FXl = actb + 1 * AE;
    __nv_bfloat16* XRh = actb + 2 * AE;
    __nv_bfloat16* XRl = actb + 3 * AE;
    __nv_bfloat16* XIh = actb + 4 * AE;
    __nv_bfloat16* XIl = actb + 5 * AE;
    __nv_bfloat16* FYh = actb + 6 * AE;
    __nv_bfloat16* FYl = actb + 7 * AE;
    __nv_bfloat16* Th  = actb + 8 * AE;
    __nv_bfloat16* Tl  = actb + 9 * AE;

    __nv_bfloat16* wb = (__nv_bfloat16*)(base + OFF_WB);
    const size_t W1E = (size_t)NP1 * KP;
    const size_t W2E = (size_t)NP2 * KP;
    const size_t WLE = 10 * W1E + 2 * W2E;

    cudaFuncSetAttribute(gemm_bf16x3, cudaFuncAttributeMaxDynamicSharedMemorySize,
                         GEMM_SMEM_BYTES);

    const int EW_BLOCKS = (int)((MD + 255) / 256);

    enc_kernel<<<EW_BLOCKS, 256>>>(x, enc_w, enc_b, H);

    {
        dim3 gw((unsigned)((W2E + 255) / 256), 6);
        for (int i = 0; i < NLAYERS; i++) {
            convw_layer_kernel<<<gw, 256>>>(
                B_re + (size_t)i*PD*DM, B_im + (size_t)i*PD*DM,
                C_re + (size_t)i*DM*PD, C_im + (size_t)i*DM*PD,
                Wdec + (size_t)i*DM*DM, Wenc + (size_t)i*2*DM*DM,
                wb + (size_t)i * WLE);
        }
    }

    dim3 g9(NP1 / 128, MROWS / 128);
    dim3 g17(NP2 / 128, MROWS / 128);
    bool padded = false;

    for (int i = 0; i < NLAYERS; i++) {
        const float* nw  = norm_w      + (size_t)i * DM;
        const float* nb  = norm_b      + (size_t)i * DM;
        const float* aw  = attn_norm_w + (size_t)i * DM;
        const float* ab  = attn_norm_b + (size_t)i * DM;
        const float* fw  = ff_norm_w   + (size_t)i * DM;
        const float* fb  = ff_norm_b   + (size_t)i * DM;
        const float* lre = lam_re      + (size_t)i * PD;
        const float* lim = lam_im      + (size_t)i * PD;
        const float* lst = log_step    + (size_t)i * PD;
        const float* dv  = Dvec        + (size_t)i * DM;

        __nv_bfloat16* L = wb + (size_t)i * WLE;
        __nv_bfloat16* Breh = L;             __nv_bfloat16* Brel = L + 1*W1E;
        __nv_bfloat16* Bimh = L + 2*W1E;     __nv_bfloat16* Biml = L + 3*W1E;
        __nv_bfloat16* Creh = L + 4*W1E;     __nv_bfloat16* Crel = L + 5*W1E;
        __nv_bfloat16* Cimh = L + 6*W1E;     __nv_bfloat16* Ciml = L + 7*W1E;
        __nv_bfloat16* Wdh  = L + 8*W1E;     __nv_bfloat16* Wdl  = L + 9*W1E;
        __nv_bfloat16* Weh  = L + 10*W1E;    __nv_bfloat16* Wel  = L + 10*W1E + W2E;

        ln2_kernel<<<MROWS, 256>>>(H, FXh, FXl, nw, nb, aw, ab);

        gemm_bf16x3<<<g9, 256, GEMM_SMEM_BYTES>>>(FXh, FXl, Breh, Brel, GRE, PD, 1.f, 0.f);
        gemm_bf16x3<<<g9, 256, GEMM_SMEM_BYTES>>>(FXh, FXl, Bimh, Biml, GIM, PD, 1.f, 0.f);

        if (!padded) {
            int npad = MROWS * (KP - DM);
            padscan_kernel<<<(npad + 255) / 256, 256>>>(XRh, XRl, XIh, XIl);
            padded = true;
        }

        scan_kernel<<<(BSZ * PD + 127) / 128, 128>>>(GRE, GIM, XRh, XRl, XIh, XIl,
                                                     lre, lim, lst);

        gemm_bf16x3<<<g9, 256, GEMM_SMEM_BYTES>>>(XRh, XRl, Creh, Crel, Y, DM, 1.f, 0.f);
        gemm_bf16x3<<<g9, 256, GEMM_SMEM_BYTES>>>(XIh, XIl, Cimh, Ciml, Y, DM, -1.f, 1.f);

        postln_kernel<<<MROWS, 256>>>(Y, FXh, FXl, dv, fw, fb, FYh, FYl);

        gemm_bf16x3<<<g17, 256, GEMM_SMEM_BYTES>>>(FYh, FYl, Weh, Wel, H2, 2 * DM, 1.f, 0.f);

        {
            size_t n = (size_t)MROWS * KP;
            geglu_kernel<<<(int)((n + 255) / 256), 256>>>(H2, Th, Tl);
        }

        gemm_bf16x3<<<g9, 256, GEMM_SMEM_BYTES>>>(Th, Tl, Wdh, Wdl, Z, DM, 1.f, 0.f);

        addres_kernel<<<EW_BLOCKS, 256>>>(H, Z, FYh, FYl);
    }

    zero_kernel<<<(BSZ * DM + 255) / 256, 256>>>(POOL, BSZ * DM);
    dim3 gp((BSZ * DM + 127) / 128, POOL_CHUNKS);
    pool_kernel<<<gp, 128>>>(H, POOL);
    head_kernel<<<BSZ, 256>>>(POOL, head_w, head_b, out);
}